// round 1
// baseline (speedup 1.0000x reference)
#include <cuda_runtime.h>
#include <cuda_bf16.h>
#include <cstdint>

// Problem constants (fixed by the dataset)
#define E_EXP 16
#define DMODEL 1024
#define DFF 2048
#define TMAX 4096
#define LN_EPS 1e-5f

#define BM 64
#define BN 32
#define BK 16

// ---------------- scratch (device globals; no allocation allowed) -------------
__device__ int   g_cnt[E_EXP];
__device__ int   g_list[E_EXP * TMAX];     // entries: pid = token*2 + slot
__device__ float g_coeff[E_EXP * TMAX];
__device__ float g_H[(size_t)2 * TMAX * DFF];     // [pid][F]  64 MB
__device__ float g_Y[(size_t)2 * TMAX * DMODEL];  // [pid][D]  32 MB

// ---------------- zero output + counters --------------------------------------
__global__ void zero_kernel(float* __restrict__ out, size_t n) {
    size_t i = (size_t)blockIdx.x * blockDim.x + threadIdx.x;
    if (i < n) out[i] = 0.f;
    if (i < E_EXP) g_cnt[i] = 0;
}

// ---------------- router: logits -> softmax -> top2 -> gather lists -----------
__global__ void __launch_bounds__(128) router_kernel(
    const float* __restrict__ x, const float* __restrict__ rw,
    const float* __restrict__ rb) {
    int t = blockIdx.x;
    __shared__ float xs[DMODEL];
    __shared__ float logits[E_EXP];
    const float* xr = x + (size_t)t * DMODEL;
    for (int i = threadIdx.x; i < DMODEL; i += blockDim.x) xs[i] = xr[i];
    __syncthreads();

    int warp = threadIdx.x >> 5, lane = threadIdx.x & 31;
    for (int e = warp; e < E_EXP; e += 4) {
        const float* w = rw + (size_t)e * DMODEL;
        float s = 0.f;
        for (int k = lane; k < DMODEL; k += 32) s += xs[k] * w[k];
        #pragma unroll
        for (int o = 16; o; o >>= 1) s += __shfl_xor_sync(0xffffffffu, s, o);
        if (lane == 0) logits[e] = s + rb[e];
    }
    __syncthreads();

    if (threadIdx.x == 0) {
        float m = -1e30f;
        #pragma unroll
        for (int e = 0; e < E_EXP; e++) m = fmaxf(m, logits[e]);
        float p[E_EXP];
        #pragma unroll
        for (int e = 0; e < E_EXP; e++) p[e] = __expf(logits[e] - m);
        // top-2 (ties -> lower index, matching lax.top_k)
        int e0 = 0;
        #pragma unroll
        for (int e = 1; e < E_EXP; e++) if (p[e] > p[e0]) e0 = e;
        int e1 = (e0 == 0) ? 1 : 0;
        #pragma unroll
        for (int e = 0; e < E_EXP; e++) {
            if (e == e0 || e == e1) continue;
            if (p[e] > p[e1]) e1 = e;
        }
        float s01 = p[e0] + p[e1];
        float c0 = p[e0] / s01, c1 = p[e1] / s01;
        int pos0 = atomicAdd(&g_cnt[e0], 1);
        g_list[e0 * TMAX + pos0] = t * 2 + 0;
        g_coeff[e0 * TMAX + pos0] = c0;
        int pos1 = atomicAdd(&g_cnt[e1], 1);
        g_list[e1 * TMAX + pos1] = t * 2 + 1;
        g_coeff[e1 * TMAX + pos1] = c1;
    }
}

// ---------------- GEMM1: H[pid] = silu(Xg @ W1^T) * (Xg @ W3^T) ----------------
__global__ void __launch_bounds__(128) gemm1_kernel(
    const float* __restrict__ x, const float* __restrict__ w1,
    const float* __restrict__ w3) {
    int e = blockIdx.z;
    int c = g_cnt[e];
    int mt = blockIdx.x;
    if (mt * BM >= c) return;
    int n0 = blockIdx.y * BN;

    __shared__ float Xs[BK][BM + 4];
    __shared__ float As[BK][BN + 4];
    __shared__ float Bs[BK][BN + 4];
    __shared__ int rows[BM];

    int tid = threadIdx.x;
    if (tid < BM) {
        int pos = mt * BM + tid;
        rows[tid] = (pos < c) ? g_list[e * TMAX + pos] : -1;
    }
    __syncthreads();

    int tr = tid >> 3;   // 0..15
    int tc = tid & 7;    // 0..7
    float acc1[4][4] = {{0}}, acc3[4][4] = {{0}};
    const float* w1e = w1 + ((size_t)e * DFF + n0) * DMODEL;
    const float* w3e = w3 + ((size_t)e * DFF + n0) * DMODEL;

    for (int k0 = 0; k0 < DMODEL; k0 += BK) {
        #pragma unroll
        for (int i = 0; i < 8; i++) {          // X tile: 64x16
            int idx = tid + i * 128;
            int r = idx >> 4, kk = idx & 15;
            int pid = rows[r];
            float v = 0.f;
            if (pid >= 0) v = x[(size_t)(pid >> 1) * DMODEL + k0 + kk];
            Xs[kk][r] = v;
        }
        #pragma unroll
        for (int i = 0; i < 4; i++) {          // W tiles: 32x16 each
            int idx = tid + i * 128;
            int r = idx >> 4, kk = idx & 15;
            As[kk][r] = w1e[(size_t)r * DMODEL + k0 + kk];
            Bs[kk][r] = w3e[(size_t)r * DMODEL + k0 + kk];
        }
        __syncthreads();
        #pragma unroll
        for (int k = 0; k < BK; k++) {
            float xr[4], wa[4], wb[4];
            #pragma unroll
            for (int i = 0; i < 4; i++) xr[i] = Xs[k][tr * 4 + i];
            #pragma unroll
            for (int j = 0; j < 4; j++) { wa[j] = As[k][tc * 4 + j]; wb[j] = Bs[k][tc * 4 + j]; }
            #pragma unroll
            for (int i = 0; i < 4; i++)
                #pragma unroll
                for (int j = 0; j < 4; j++) {
                    acc1[i][j] += xr[i] * wa[j];
                    acc3[i][j] += xr[i] * wb[j];
                }
        }
        __syncthreads();
    }

    #pragma unroll
    for (int i = 0; i < 4; i++) {
        int r = tr * 4 + i;
        int pid = rows[r];
        if (pid < 0) continue;
        float* hrow = g_H + (size_t)pid * DFF + n0;
        #pragma unroll
        for (int j = 0; j < 4; j++) {
            float z = acc1[i][j];
            float s = z / (1.f + __expf(-z));   // silu
            hrow[tc * 4 + j] = s * acc3[i][j];
        }
    }
}

// ---------------- GEMM2: Y[pid] = Hg @ W2^T ------------------------------------
__global__ void __launch_bounds__(128) gemm2_kernel(const float* __restrict__ w2) {
    int e = blockIdx.z;
    int c = g_cnt[e];
    int mt = blockIdx.x;
    if (mt * BM >= c) return;
    int n0 = blockIdx.y * BN;

    __shared__ float Hs[BK][BM + 4];
    __shared__ float Ws[BK][BN + 4];
    __shared__ int rows[BM];

    int tid = threadIdx.x;
    if (tid < BM) {
        int pos = mt * BM + tid;
        rows[tid] = (pos < c) ? g_list[e * TMAX + pos] : -1;
    }
    __syncthreads();

    int tr = tid >> 3, tc = tid & 7;
    float acc[4][4] = {{0}};
    const float* w2e = w2 + ((size_t)e * DMODEL + n0) * DFF;

    for (int k0 = 0; k0 < DFF; k0 += BK) {
        #pragma unroll
        for (int i = 0; i < 8; i++) {
            int idx = tid + i * 128;
            int r = idx >> 4, kk = idx & 15;
            int pid = rows[r];
            float v = 0.f;
            if (pid >= 0) v = g_H[(size_t)pid * DFF + k0 + kk];
            Hs[kk][r] = v;
        }
        #pragma unroll
        for (int i = 0; i < 4; i++) {
            int idx = tid + i * 128;
            int r = idx >> 4, kk = idx & 15;
            Ws[kk][r] = w2e[(size_t)r * DFF + k0 + kk];
        }
        __syncthreads();
        #pragma unroll
        for (int k = 0; k < BK; k++) {
            float hr[4], wv[4];
            #pragma unroll
            for (int i = 0; i < 4; i++) hr[i] = Hs[k][tr * 4 + i];
            #pragma unroll
            for (int j = 0; j < 4; j++) wv[j] = Ws[k][tc * 4 + j];
            #pragma unroll
            for (int i = 0; i < 4; i++)
                #pragma unroll
                for (int j = 0; j < 4; j++) acc[i][j] += hr[i] * wv[j];
        }
        __syncthreads();
    }

    #pragma unroll
    for (int i = 0; i < 4; i++) {
        int r = tr * 4 + i;
        int pid = rows[r];
        if (pid < 0) continue;
        float* yrow = g_Y + (size_t)pid * DMODEL + n0;
        #pragma unroll
        for (int j = 0; j < 4; j++) yrow[tc * 4 + j] = acc[i][j];
    }
}

// ---------------- LayerNorm + coeff scale + scatter-add ------------------------
__global__ void __launch_bounds__(256) ln_kernel(
    const float* __restrict__ ln_g, const float* __restrict__ ln_b,
    float* __restrict__ out) {
    int pos = blockIdx.x;
    __shared__ float red[8];
    __shared__ float bval;

    for (int e = 0; e < E_EXP; e++) {
        __syncthreads();
        if (pos >= g_cnt[e]) continue;   // uniform per block
        int pid = g_list[e * TMAX + pos];
        float c = g_coeff[e * TMAX + pos];
        int t = pid >> 1;
        const float* yr = g_Y + (size_t)pid * DMODEL;

        float v[4];
        float s = 0.f;
        #pragma unroll
        for (int i = 0; i < 4; i++) { v[i] = yr[threadIdx.x + i * 256]; s += v[i]; }
        int lane = threadIdx.x & 31, warp = threadIdx.x >> 5;
        #pragma unroll
        for (int o = 16; o; o >>= 1) s += __shfl_xor_sync(0xffffffffu, s, o);
        if (lane == 0) red[warp] = s;
        __syncthreads();
        float tot = 0.f;
        #pragma unroll
        for (int i = 0; i < 8; i++) tot += red[i];
        float mu = tot * (1.f / DMODEL);
        __syncthreads();

        float q = 0.f;
        #pragma unroll
        for (int i = 0; i < 4; i++) { float d = v[i] - mu; q += d * d; }
        #pragma unroll
        for (int o = 16; o; o >>= 1) q += __shfl_xor_sync(0xffffffffu, q, o);
        if (lane == 0) red[warp] = q;
        __syncthreads();
        float qt = 0.f;
        #pragma unroll
        for (int i = 0; i < 8; i++) qt += red[i];
        float rstd = rsqrtf(qt * (1.f / DMODEL) + LN_EPS);
        (void)bval;

        const float* g = ln_g + (size_t)e * DMODEL;
        const float* b = ln_b + (size_t)e * DMODEL;
        #pragma unroll
        for (int i = 0; i < 4; i++) {
            int col = threadIdx.x + i * 256;
            float yn = (v[i] - mu) * rstd * g[col] + b[col];
            atomicAdd(&out[(size_t)t * DMODEL + col], c * yn);
        }
    }
}

// ---------------- launch --------------------------------------------------------
extern "C" void kernel_launch(void* const* d_in, const int* in_sizes, int n_in,
                              void* d_out, int out_size) {
    const float* x  = (const float*)d_in[0];
    const float* rw = (const float*)d_in[1];
    const float* rb = (const float*)d_in[2];
    const float* w1 = (const float*)d_in[3];
    const float* w2 = (const float*)d_in[4];
    const float* w3 = (const float*)d_in[5];
    const float* lg = (const float*)d_in[6];
    const float* lb = (const float*)d_in[7];
    float* out = (float*)d_out;

    int T = in_sizes[0] / DMODEL;   // 4096
    size_t n = (size_t)T * DMODEL;

    zero_kernel<<<(unsigned)((n + 255) / 256), 256>>>(out, n);
    router_kernel<<<T, 128>>>(x, rw, rb);

    dim3 g1((T + BM - 1) / BM, DFF / BN, E_EXP);
    gemm1_kernel<<<g1, 128>>>(x, w1, w3);

    dim3 g2((T + BM - 1) / BM, DMODEL / BN, E_EXP);
    gemm2_kernel<<<g2, 128>>>(w2);

    ln_kernel<<<T, 256>>>(lg, lb, out);
}

// round 3
// speedup vs baseline: 2.7359x; 2.7359x over previous
#include <cuda_runtime.h>
#include <cuda_bf16.h>
#include <cstdint>

// Problem constants
#define E_EXP 16
#define DMODEL 1024
#define DFF 2048
#define TMAX 4096
#define LN_EPS 1e-5f

#define BK 32          // fp32 elements per K-chunk
#define SA 40          // smem row stride in bf16 elements (32 + 8 pad)

// ---------------- scratch (device globals) ------------------------------------
__device__ int   g_cnt[E_EXP];
__device__ int   g_list[E_EXP * TMAX];     // entries: pid = token*2 + slot
__device__ float g_coeff[E_EXP * TMAX];
__device__ float g_H[(size_t)2 * TMAX * DFF];     // [pid][F]
__device__ float g_Y[(size_t)2 * TMAX * DMODEL];  // [pid][D]

// ---------------- helpers -------------------------------------------------------
__device__ __forceinline__ void mma_bf16(float* c, uint32_t a0, uint32_t a1,
                                         uint32_t a2, uint32_t a3,
                                         uint32_t b0, uint32_t b1) {
    asm volatile(
        "mma.sync.aligned.m16n8k16.row.col.f32.bf16.bf16.f32 "
        "{%0,%1,%2,%3}, {%4,%5,%6,%7}, {%8,%9}, {%0,%1,%2,%3};\n"
        : "+f"(c[0]), "+f"(c[1]), "+f"(c[2]), "+f"(c[3])
        : "r"(a0), "r"(a1), "r"(a2), "r"(a3), "r"(b0), "r"(b1));
}

// split two fp32 into packed bf16 hi pair and lo pair (x in low 16 bits)
__device__ __forceinline__ void split2(float x, float y, uint32_t& h, uint32_t& l) {
    __nv_bfloat16 hx = __float2bfloat16(x);
    __nv_bfloat16 hy = __float2bfloat16(y);
    __nv_bfloat16 lx = __float2bfloat16(x - __bfloat162float(hx));
    __nv_bfloat16 ly = __float2bfloat16(y - __bfloat162float(hy));
    h = (uint32_t)__bfloat16_as_ushort(hx) | ((uint32_t)__bfloat16_as_ushort(hy) << 16);
    l = (uint32_t)__bfloat16_as_ushort(lx) | ((uint32_t)__bfloat16_as_ushort(ly) << 16);
}

__device__ __forceinline__ uint32_t lds32(const __nv_bfloat16* p) {
    return *(const uint32_t*)p;
}

// ---------------- zero output + counters --------------------------------------
__global__ void zero_kernel(float* __restrict__ out, size_t n) {
    size_t i = (size_t)blockIdx.x * blockDim.x + threadIdx.x;
    if (i < n) out[i] = 0.f;
    if (i < E_EXP) g_cnt[i] = 0;
}

// ---------------- router --------------------------------------------------------
__global__ void __launch_bounds__(128) router_kernel(
    const float* __restrict__ x, const float* __restrict__ rw,
    const float* __restrict__ rb) {
    int t = blockIdx.x;
    __shared__ float xs[DMODEL];
    __shared__ float logits[E_EXP];
    const float* xr = x + (size_t)t * DMODEL;
    for (int i = threadIdx.x; i < DMODEL; i += blockDim.x) xs[i] = xr[i];
    __syncthreads();

    int warp = threadIdx.x >> 5, lane = threadIdx.x & 31;
    for (int e = warp; e < E_EXP; e += 4) {
        const float* w = rw + (size_t)e * DMODEL;
        float s = 0.f;
        for (int k = lane; k < DMODEL; k += 32) s += xs[k] * w[k];
        #pragma unroll
        for (int o = 16; o; o >>= 1) s += __shfl_xor_sync(0xffffffffu, s, o);
        if (lane == 0) logits[e] = s + rb[e];
    }
    __syncthreads();

    if (threadIdx.x == 0) {
        float m = -1e30f;
        #pragma unroll
        for (int e = 0; e < E_EXP; e++) m = fmaxf(m, logits[e]);
        float p[E_EXP];
        #pragma unroll
        for (int e = 0; e < E_EXP; e++) p[e] = __expf(logits[e] - m);
        int e0 = 0;
        #pragma unroll
        for (int e = 1; e < E_EXP; e++) if (p[e] > p[e0]) e0 = e;
        int e1 = (e0 == 0) ? 1 : 0;
        #pragma unroll
        for (int e = 0; e < E_EXP; e++) {
            if (e == e0 || e == e1) continue;
            if (p[e] > p[e1]) e1 = e;
        }
        float s01 = p[e0] + p[e1];
        int pos0 = atomicAdd(&g_cnt[e0], 1);
        g_list[e0 * TMAX + pos0] = t * 2 + 0;
        g_coeff[e0 * TMAX + pos0] = p[e0] / s01;
        int pos1 = atomicAdd(&g_cnt[e1], 1);
        g_list[e1 * TMAX + pos1] = t * 2 + 1;
        g_coeff[e1 * TMAX + pos1] = p[e1] / s01;
    }
}

// smem stage layout (bf16 element offsets), GEMM1:
//   Ah:  0                (128 x SA)
//   Al:  128*SA           (128 x SA)
//   W1h: 256*SA           (64 x SA)
//   W1l: 320*SA
//   W3h: 384*SA
//   W3l: 448*SA
// stage total = 512*SA bf16 = 512*40*2 = 40960 bytes
#define G1_STAGE_ELEMS (512 * SA)
#define G1_SMEM (2 * G1_STAGE_ELEMS * 2)

// =====================  GEMM1: H = silu(Xg W1^T) * (Xg W3^T)  ==================
__global__ void __launch_bounds__(256) gemm1_tc(
    const float* __restrict__ x, const float* __restrict__ w1,
    const float* __restrict__ w3) {
    int e = blockIdx.z;
    int c = g_cnt[e];
    int mt0 = blockIdx.x;
    if (mt0 * 128 >= c) return;
    int n0 = blockIdx.y * 64;

    extern __shared__ __align__(16) __nv_bfloat16 smem[];
    __shared__ int rows[128];

    int tid = threadIdx.x;
    if (tid < 128) {
        int pos = mt0 * 128 + tid;
        rows[tid] = (pos < c) ? g_list[e * TMAX + pos] : -1;
    }
    __syncthreads();

    const float* w1e = w1 + ((size_t)e * DFF + n0) * DMODEL;
    const float* w3e = w3 + ((size_t)e * DFF + n0) * DMODEL;

    int lane = tid & 31, warp = tid >> 5;
    int warp_m = warp & 3, warp_n = warp >> 2;     // 4x2 warp grid
    int g = lane >> 2, t4 = lane & 3;

    float acc1[2][4][4], acc3[2][4][4];
    #pragma unroll
    for (int i = 0; i < 2; i++)
        #pragma unroll
        for (int j = 0; j < 4; j++)
            #pragma unroll
            for (int k = 0; k < 4; k++) { acc1[i][j][k] = 0.f; acc3[i][j][k] = 0.f; }

    float4 ar[4], w1r[2], w3r[2];

    auto LOAD = [&](int s) {
        #pragma unroll
        for (int i = 0; i < 4; i++) {
            int slot = tid + 256 * i, r = slot >> 3, c4 = slot & 7;
            int pid = rows[r];
            ar[i] = (pid >= 0)
                ? *(const float4*)(x + (size_t)(pid >> 1) * DMODEL + s * BK + c4 * 4)
                : make_float4(0.f, 0.f, 0.f, 0.f);
        }
        #pragma unroll
        for (int i = 0; i < 2; i++) {
            int slot = tid + 256 * i, r = slot >> 3, c4 = slot & 7;
            w1r[i] = *(const float4*)(w1e + (size_t)r * DMODEL + s * BK + c4 * 4);
            w3r[i] = *(const float4*)(w3e + (size_t)r * DMODEL + s * BK + c4 * 4);
        }
    };

    auto STORE = [&](int p) {
        __nv_bfloat16* st = smem + p * G1_STAGE_ELEMS;
        #pragma unroll
        for (int i = 0; i < 4; i++) {
            int slot = tid + 256 * i, r = slot >> 3, c4 = slot & 7;
            uint32_t h0, l0, h1, l1;
            split2(ar[i].x, ar[i].y, h0, l0);
            split2(ar[i].z, ar[i].w, h1, l1);
            uint32_t off = r * SA + c4 * 4;
            *(uint2*)(st + off)            = make_uint2(h0, h1);
            *(uint2*)(st + 128 * SA + off) = make_uint2(l0, l1);
        }
        #pragma unroll
        for (int i = 0; i < 2; i++) {
            int slot = tid + 256 * i, r = slot >> 3, c4 = slot & 7;
            uint32_t off = r * SA + c4 * 4;
            uint32_t h0, l0, h1, l1;
            split2(w1r[i].x, w1r[i].y, h0, l0);
            split2(w1r[i].z, w1r[i].w, h1, l1);
            *(uint2*)(st + 256 * SA + off) = make_uint2(h0, h1);
            *(uint2*)(st + 320 * SA + off) = make_uint2(l0, l1);
            split2(w3r[i].x, w3r[i].y, h0, l0);
            split2(w3r[i].z, w3r[i].w, h1, l1);
            *(uint2*)(st + 384 * SA + off) = make_uint2(h0, h1);
            *(uint2*)(st + 448 * SA + off) = make_uint2(l0, l1);
        }
    };

    LOAD(0);
    const int NS = DMODEL / BK;   // 32
    for (int s = 0; s < NS; s++) {
        int p = s & 1;
        STORE(p);
        __syncthreads();
        if (s + 1 < NS) LOAD(s + 1);

        const __nv_bfloat16* st = smem + p * G1_STAGE_ELEMS;
        const __nv_bfloat16* Ah = st;
        const __nv_bfloat16* Al = st + 128 * SA;
        #pragma unroll
        for (int ks = 0; ks < 2; ks++) {
            int col = ks * 16 + 2 * t4;
            uint32_t ah[2][4], al[2][4];
            #pragma unroll
            for (int mt = 0; mt < 2; mt++) {
                int r0 = warp_m * 32 + mt * 16 + g;
                ah[mt][0] = lds32(Ah + r0 * SA + col);
                ah[mt][1] = lds32(Ah + (r0 + 8) * SA + col);
                ah[mt][2] = lds32(Ah + r0 * SA + col + 8);
                ah[mt][3] = lds32(Ah + (r0 + 8) * SA + col + 8);
                al[mt][0] = lds32(Al + r0 * SA + col);
                al[mt][1] = lds32(Al + (r0 + 8) * SA + col);
                al[mt][2] = lds32(Al + r0 * SA + col + 8);
                al[mt][3] = lds32(Al + (r0 + 8) * SA + col + 8);
            }
            #pragma unroll
            for (int nt = 0; nt < 4; nt++) {
                int n = warp_n * 32 + nt * 8 + g;
                uint32_t b1h0 = lds32(st + 256 * SA + n * SA + col);
                uint32_t b1h1 = lds32(st + 256 * SA + n * SA + col + 8);
                uint32_t b1l0 = lds32(st + 320 * SA + n * SA + col);
                uint32_t b1l1 = lds32(st + 320 * SA + n * SA + col + 8);
                uint32_t b3h0 = lds32(st + 384 * SA + n * SA + col);
                uint32_t b3h1 = lds32(st + 384 * SA + n * SA + col + 8);
                uint32_t b3l0 = lds32(st + 448 * SA + n * SA + col);
                uint32_t b3l1 = lds32(st + 448 * SA + n * SA + col + 8);
                #pragma unroll
                for (int mt = 0; mt < 2; mt++) {
                    mma_bf16(acc1[mt][nt], ah[mt][0], ah[mt][1], ah[mt][2], ah[mt][3], b1h0, b1h1);
                    mma_bf16(acc1[mt][nt], ah[mt][0], ah[mt][1], ah[mt][2], ah[mt][3], b1l0, b1l1);
                    mma_bf16(acc1[mt][nt], al[mt][0], al[mt][1], al[mt][2], al[mt][3], b1h0, b1h1);
                    mma_bf16(acc3[mt][nt], ah[mt][0], ah[mt][1], ah[mt][2], ah[mt][3], b3h0, b3h1);
                    mma_bf16(acc3[mt][nt], ah[mt][0], ah[mt][1], ah[mt][2], ah[mt][3], b3l0, b3l1);
                    mma_bf16(acc3[mt][nt], al[mt][0], al[mt][1], al[mt][2], al[mt][3], b3h0, b3h1);
                }
            }
        }
        __syncthreads();
    }

    // epilogue: silu(acc1) * acc3 -> g_H
    #pragma unroll
    for (int mt = 0; mt < 2; mt++) {
        int rl = warp_m * 32 + mt * 16 + g;
        int pid0 = rows[rl], pid1 = rows[rl + 8];
        #pragma unroll
        for (int nt = 0; nt < 4; nt++) {
            int col = n0 + warp_n * 32 + nt * 8 + 2 * t4;
            if (pid0 >= 0) {
                float z0 = acc1[mt][nt][0], z1 = acc1[mt][nt][1];
                float2 o;
                o.x = z0 / (1.f + __expf(-z0)) * acc3[mt][nt][0];
                o.y = z1 / (1.f + __expf(-z1)) * acc3[mt][nt][1];
                *(float2*)(g_H + (size_t)pid0 * DFF + col) = o;
            }
            if (pid1 >= 0) {
                float z2 = acc1[mt][nt][2], z3 = acc1[mt][nt][3];
                float2 o;
                o.x = z2 / (1.f + __expf(-z2)) * acc3[mt][nt][2];
                o.y = z3 / (1.f + __expf(-z3)) * acc3[mt][nt][3];
                *(float2*)(g_H + (size_t)pid1 * DFF + col) = o;
            }
        }
    }
}

// smem stage layout GEMM2: Ah 0, Al 128*SA, Wh 256*SA, Wl 320*SA -> 384*SA elems
#define G2_STAGE_ELEMS (384 * SA)
#define G2_SMEM (2 * G2_STAGE_ELEMS * 2)

// =====================  GEMM2: Y = Hg W2^T  ====================================
__global__ void __launch_bounds__(256) gemm2_tc(const float* __restrict__ w2) {
    int e = blockIdx.z;
    int c = g_cnt[e];
    int mt0 = blockIdx.x;
    if (mt0 * 128 >= c) return;
    int n0 = blockIdx.y * 64;

    extern __shared__ __align__(16) __nv_bfloat16 smem[];
    __shared__ int rows[128];

    int tid = threadIdx.x;
    if (tid < 128) {
        int pos = mt0 * 128 + tid;
        rows[tid] = (pos < c) ? g_list[e * TMAX + pos] : -1;
    }
    __syncthreads();

    const float* w2e = w2 + ((size_t)e * DMODEL + n0) * DFF;

    int lane = tid & 31, warp = tid >> 5;
    int warp_m = warp & 3, warp_n = warp >> 2;
    int g = lane >> 2, t4 = lane & 3;

    float acc[2][4][4];
    #pragma unroll
    for (int i = 0; i < 2; i++)
        #pragma unroll
        for (int j = 0; j < 4; j++)
            #pragma unroll
            for (int k = 0; k < 4; k++) acc[i][j][k] = 0.f;

    float4 ar[4], wr[2];

    auto LOAD = [&](int s) {
        #pragma unroll
        for (int i = 0; i < 4; i++) {
            int slot = tid + 256 * i, r = slot >> 3, c4 = slot & 7;
            int pid = rows[r];
            ar[i] = (pid >= 0)
                ? *(const float4*)(g_H + (size_t)pid * DFF + s * BK + c4 * 4)
                : make_float4(0.f, 0.f, 0.f, 0.f);
        }
        #pragma unroll
        for (int i = 0; i < 2; i++) {
            int slot = tid + 256 * i, r = slot >> 3, c4 = slot & 7;
            wr[i] = *(const float4*)(w2e + (size_t)r * DFF + s * BK + c4 * 4);
        }
    };

    auto STORE = [&](int p) {
        __nv_bfloat16* st = smem + p * G2_STAGE_ELEMS;
        #pragma unroll
        for (int i = 0; i < 4; i++) {
            int slot = tid + 256 * i, r = slot >> 3, c4 = slot & 7;
            uint32_t h0, l0, h1, l1;
            split2(ar[i].x, ar[i].y, h0, l0);
            split2(ar[i].z, ar[i].w, h1, l1);
            uint32_t off = r * SA + c4 * 4;
            *(uint2*)(st + off)            = make_uint2(h0, h1);
            *(uint2*)(st + 128 * SA + off) = make_uint2(l0, l1);
        }
        #pragma unroll
        for (int i = 0; i < 2; i++) {
            int slot = tid + 256 * i, r = slot >> 3, c4 = slot & 7;
            uint32_t off = r * SA + c4 * 4;
            uint32_t h0, l0, h1, l1;
            split2(wr[i].x, wr[i].y, h0, l0);
            split2(wr[i].z, wr[i].w, h1, l1);
            *(uint2*)(st + 256 * SA + off) = make_uint2(h0, h1);
            *(uint2*)(st + 320 * SA + off) = make_uint2(l0, l1);
        }
    };

    LOAD(0);
    const int NS = DFF / BK;   // 64
    for (int s = 0; s < NS; s++) {
        int p = s & 1;
        STORE(p);
        __syncthreads();
        if (s + 1 < NS) LOAD(s + 1);

        const __nv_bfloat16* st = smem + p * G2_STAGE_ELEMS;
        const __nv_bfloat16* Ah = st;
        const __nv_bfloat16* Al = st + 128 * SA;
        #pragma unroll
        for (int ks = 0; ks < 2; ks++) {
            int col = ks * 16 + 2 * t4;
            uint32_t ah[2][4], al[2][4];
            #pragma unroll
            for (int mt = 0; mt < 2; mt++) {
                int r0 = warp_m * 32 + mt * 16 + g;
                ah[mt][0] = lds32(Ah + r0 * SA + col);
                ah[mt][1] = lds32(Ah + (r0 + 8) * SA + col);
                ah[mt][2] = lds32(Ah + r0 * SA + col + 8);
                ah[mt][3] = lds32(Ah + (r0 + 8) * SA + col + 8);
                al[mt][0] = lds32(Al + r0 * SA + col);
                al[mt][1] = lds32(Al + (r0 + 8) * SA + col);
                al[mt][2] = lds32(Al + r0 * SA + col + 8);
                al[mt][3] = lds32(Al + (r0 + 8) * SA + col + 8);
            }
            #pragma unroll
            for (int nt = 0; nt < 4; nt++) {
                int n = warp_n * 32 + nt * 8 + g;
                uint32_t bh0 = lds32(st + 256 * SA + n * SA + col);
                uint32_t bh1 = lds32(st + 256 * SA + n * SA + col + 8);
                uint32_t bl0 = lds32(st + 320 * SA + n * SA + col);
                uint32_t bl1 = lds32(st + 320 * SA + n * SA + col + 8);
                #pragma unroll
                for (int mt = 0; mt < 2; mt++) {
                    mma_bf16(acc[mt][nt], ah[mt][0], ah[mt][1], ah[mt][2], ah[mt][3], bh0, bh1);
                    mma_bf16(acc[mt][nt], ah[mt][0], ah[mt][1], ah[mt][2], ah[mt][3], bl0, bl1);
                    mma_bf16(acc[mt][nt], al[mt][0], al[mt][1], al[mt][2], al[mt][3], bh0, bh1);
                }
            }
        }
        __syncthreads();
    }

    #pragma unroll
    for (int mt = 0; mt < 2; mt++) {
        int rl = warp_m * 32 + mt * 16 + g;
        int pid0 = rows[rl], pid1 = rows[rl + 8];
        #pragma unroll
        for (int nt = 0; nt < 4; nt++) {
            int col = n0 + warp_n * 32 + nt * 8 + 2 * t4;
            if (pid0 >= 0)
                *(float2*)(g_Y + (size_t)pid0 * DMODEL + col) =
                    make_float2(acc[mt][nt][0], acc[mt][nt][1]);
            if (pid1 >= 0)
                *(float2*)(g_Y + (size_t)pid1 * DMODEL + col) =
                    make_float2(acc[mt][nt][2], acc[mt][nt][3]);
        }
    }
}

// ---------------- LayerNorm + coeff scale + scatter-add ------------------------
__global__ void __launch_bounds__(256) ln_kernel(
    const float* __restrict__ ln_g, const float* __restrict__ ln_b,
    float* __restrict__ out) {
    int pos = blockIdx.x;
    __shared__ float red[8];

    for (int e = 0; e < E_EXP; e++) {
        __syncthreads();
        if (pos >= g_cnt[e]) continue;
        int pid = g_list[e * TMAX + pos];
        float cf = g_coeff[e * TMAX + pos];
        int t = pid >> 1;
        const float* yr = g_Y + (size_t)pid * DMODEL;

        float v[4];
        float s = 0.f;
        #pragma unroll
        for (int i = 0; i < 4; i++) { v[i] = yr[threadIdx.x + i * 256]; s += v[i]; }
        int lane = threadIdx.x & 31, warp = threadIdx.x >> 5;
        #pragma unroll
        for (int o = 16; o; o >>= 1) s += __shfl_xor_sync(0xffffffffu, s, o);
        if (lane == 0) red[warp] = s;
        __syncthreads();
        float tot = 0.f;
        #pragma unroll
        for (int i = 0; i < 8; i++) tot += red[i];
        float mu = tot * (1.f / DMODEL);
        __syncthreads();

        float q = 0.f;
        #pragma unroll
        for (int i = 0; i < 4; i++) { float d = v[i] - mu; q += d * d; }
        #pragma unroll
        for (int o = 16; o; o >>= 1) q += __shfl_xor_sync(0xffffffffu, q, o);
        if (lane == 0) red[warp] = q;
        __syncthreads();
        float qt = 0.f;
        #pragma unroll
        for (int i = 0; i < 8; i++) qt += red[i];
        float rstd = rsqrtf(qt * (1.f / DMODEL) + LN_EPS);

        const float* g = ln_g + (size_t)e * DMODEL;
        const float* b = ln_b + (size_t)e * DMODEL;
        #pragma unroll
        for (int i = 0; i < 4; i++) {
            int col = threadIdx.x + i * 256;
            float yn = (v[i] - mu) * rstd * g[col] + b[col];
            atomicAdd(&out[(size_t)t * DMODEL + col], cf * yn);
        }
    }
}

// ---------------- launch --------------------------------------------------------
extern "C" void kernel_launch(void* const* d_in, const int* in_sizes, int n_in,
                              void* d_out, int out_size) {
    const float* x  = (const float*)d_in[0];
    const float* rw = (const float*)d_in[1];
    const float* rb = (const float*)d_in[2];
    const float* w1 = (const float*)d_in[3];
    const float* w2 = (const float*)d_in[4];
    const float* w3 = (const float*)d_in[5];
    const float* lg = (const float*)d_in[6];
    const float* lb = (const float*)d_in[7];
    float* out = (float*)d_out;

    int T = in_sizes[0] / DMODEL;   // 4096
    size_t n = (size_t)T * DMODEL;

    static bool attr_set = false;
    if (!attr_set) {
        cudaFuncSetAttribute(gemm1_tc, cudaFuncAttributeMaxDynamicSharedMemorySize, G1_SMEM);
        cudaFuncSetAttribute(gemm2_tc, cudaFuncAttributeMaxDynamicSharedMemorySize, G2_SMEM);
        attr_set = true;
    }

    zero_kernel<<<(unsigned)((n + 255) / 256), 256>>>(out, n);
    router_kernel<<<T, 128>>>(x, rw, rb);

    dim3 g1((T + 127) / 128, DFF / 64, E_EXP);
    gemm1_tc<<<g1, 256, G1_SMEM>>>(x, w1, w3);

    dim3 g2((T + 127) / 128, DMODEL / 64, E_EXP);
    gemm2_tc<<<g2, 256, G2_SMEM>>>(w2);

    ln_kernel<<<T, 256>>>(lg, lb, out);
}

// round 4
// speedup vs baseline: 2.9151x; 1.0655x over previous
#include <cuda_runtime.h>
#include <cuda_bf16.h>
#include <cstdint>

// Problem constants
#define E_EXP 16
#define DMODEL 1024
#define DFF 2048
#define TMAX 4096
#define LN_EPS 1e-5f

#define BK 32          // fp32 elements per K-chunk
#define SA 40          // smem row stride in bf16 elements (32 + 8 pad)
#define SA2 80         // stride in bytes

// ---------------- scratch (device globals) ------------------------------------
__device__ int   g_cnt[E_EXP];
__device__ int   g_list[E_EXP * TMAX];     // entries: pid = token*2 + slot
__device__ float g_coeff[E_EXP * TMAX];
__device__ float g_H[(size_t)2 * TMAX * DFF];     // [pid][F]
__device__ float g_Y[(size_t)2 * TMAX * DMODEL];  // [pid][D]

// ---------------- helpers -------------------------------------------------------
__device__ __forceinline__ uint32_t smem_u32(const void* p) {
    uint32_t a;
    asm("{ .reg .u64 t; cvta.to.shared.u64 t, %1; cvt.u32.u64 %0, t; }" : "=r"(a) : "l"(p));
    return a;
}

__device__ __forceinline__ void mma_bf16(float* c, const uint32_t* a,
                                         uint32_t b0, uint32_t b1) {
    asm volatile(
        "mma.sync.aligned.m16n8k16.row.col.f32.bf16.bf16.f32 "
        "{%0,%1,%2,%3}, {%4,%5,%6,%7}, {%8,%9}, {%0,%1,%2,%3};\n"
        : "+f"(c[0]), "+f"(c[1]), "+f"(c[2]), "+f"(c[3])
        : "r"(a[0]), "r"(a[1]), "r"(a[2]), "r"(a[3]), "r"(b0), "r"(b1));
}

__device__ __forceinline__ void ldsm4(uint32_t* r, uint32_t a) {
    asm volatile("ldmatrix.sync.aligned.m8n8.x4.shared.b16 {%0,%1,%2,%3}, [%4];"
        : "=r"(r[0]), "=r"(r[1]), "=r"(r[2]), "=r"(r[3]) : "r"(a));
}

// split two fp32 into packed bf16 hi pair and lo pair
__device__ __forceinline__ void split2(float x, float y, uint32_t& h, uint32_t& l) {
    __nv_bfloat16 hx = __float2bfloat16(x);
    __nv_bfloat16 hy = __float2bfloat16(y);
    __nv_bfloat16 lx = __float2bfloat16(x - __bfloat162float(hx));
    __nv_bfloat16 ly = __float2bfloat16(y - __bfloat162float(hy));
    h = (uint32_t)__bfloat16_as_ushort(hx) | ((uint32_t)__bfloat16_as_ushort(hy) << 16);
    l = (uint32_t)__bfloat16_as_ushort(lx) | ((uint32_t)__bfloat16_as_ushort(ly) << 16);
}

// ---------------- zero output + counters --------------------------------------
__global__ void zero_kernel(float* __restrict__ out, size_t n) {
    size_t i = (size_t)blockIdx.x * blockDim.x + threadIdx.x;
    if (i < n) out[i] = 0.f;
    if (i < E_EXP) g_cnt[i] = 0;
}

// ---------------- router --------------------------------------------------------
__global__ void __launch_bounds__(128) router_kernel(
    const float* __restrict__ x, const float* __restrict__ rw,
    const float* __restrict__ rb) {
    int t = blockIdx.x;
    __shared__ float xs[DMODEL];
    __shared__ float logits[E_EXP];
    const float* xr = x + (size_t)t * DMODEL;
    for (int i = threadIdx.x; i < DMODEL; i += blockDim.x) xs[i] = xr[i];
    __syncthreads();

    int warp = threadIdx.x >> 5, lane = threadIdx.x & 31;
    for (int e = warp; e < E_EXP; e += 4) {
        const float* w = rw + (size_t)e * DMODEL;
        float s = 0.f;
        for (int k = lane; k < DMODEL; k += 32) s += xs[k] * w[k];
        #pragma unroll
        for (int o = 16; o; o >>= 1) s += __shfl_xor_sync(0xffffffffu, s, o);
        if (lane == 0) logits[e] = s + rb[e];
    }
    __syncthreads();

    if (threadIdx.x == 0) {
        float m = -1e30f;
        #pragma unroll
        for (int e = 0; e < E_EXP; e++) m = fmaxf(m, logits[e]);
        float p[E_EXP];
        #pragma unroll
        for (int e = 0; e < E_EXP; e++) p[e] = __expf(logits[e] - m);
        int e0 = 0;
        #pragma unroll
        for (int e = 1; e < E_EXP; e++) if (p[e] > p[e0]) e0 = e;
        int e1 = (e0 == 0) ? 1 : 0;
        #pragma unroll
        for (int e = 0; e < E_EXP; e++) {
            if (e == e0 || e == e1) continue;
            if (p[e] > p[e1]) e1 = e;
        }
        float s01 = p[e0] + p[e1];
        int pos0 = atomicAdd(&g_cnt[e0], 1);
        g_list[e0 * TMAX + pos0] = t * 2 + 0;
        g_coeff[e0 * TMAX + pos0] = p[e0] / s01;
        int pos1 = atomicAdd(&g_cnt[e1], 1);
        g_list[e1 * TMAX + pos1] = t * 2 + 1;
        g_coeff[e1 * TMAX + pos1] = p[e1] / s01;
    }
}

// stage byte offsets (element layout: rows of SA bf16)
//   Ah: 0   Al: 128*SA   [gemm1: W1h 256*SA, W1l 320*SA, W3h 384*SA, W3l 448*SA]
#define G1_STAGE_ELEMS (512 * SA)
#define G1_SMEM (2 * G1_STAGE_ELEMS * 2)
#define G2_STAGE_ELEMS (384 * SA)
#define G2_SMEM (2 * G2_STAGE_ELEMS * 2)

// =====================  GEMM1: H = silu(Xg W1^T) * (Xg W3^T)  ==================
__global__ void __launch_bounds__(256) gemm1_tc(
    const float* __restrict__ x, const float* __restrict__ w1,
    const float* __restrict__ w3) {
    int e = blockIdx.z;
    int c = g_cnt[e];
    int mt0 = blockIdx.x;
    if (mt0 * 128 >= c) return;
    int n0 = blockIdx.y * 64;

    extern __shared__ __align__(16) __nv_bfloat16 smem[];
    __shared__ int rows[128];

    int tid = threadIdx.x;
    if (tid < 128) {
        int pos = mt0 * 128 + tid;
        rows[tid] = (pos < c) ? g_list[e * TMAX + pos] : -1;
    }
    __syncthreads();

    const float* w1e = w1 + ((size_t)e * DFF + n0) * DMODEL;
    const float* w3e = w3 + ((size_t)e * DFF + n0) * DMODEL;

    int lane = tid & 31, warp = tid >> 5;
    int warp_m = warp & 3, warp_n = warp >> 2;     // 4x2 warp grid
    int g = lane >> 2, t4 = lane & 3;

    uint32_t sb = smem_u32(smem);
    // ldmatrix per-lane byte offsets
    uint32_t aoff = (uint32_t)((warp_m * 32 + (lane & 15)) * SA2 + ((lane >> 4) * 16));
    uint32_t boff = (uint32_t)((warp_n * 32 + (lane & 7) + ((lane & 16) ? 8 : 0)) * SA2 +
                               ((lane & 8) ? 16 : 0));

    float acc1[2][4][4], acc3[2][4][4];
    #pragma unroll
    for (int i = 0; i < 2; i++)
        #pragma unroll
        for (int j = 0; j < 4; j++)
            #pragma unroll
            for (int k = 0; k < 4; k++) { acc1[i][j][k] = 0.f; acc3[i][j][k] = 0.f; }

    float4 ar[4], w1r[2], w3r[2];

    auto LOAD = [&](int s) {
        #pragma unroll
        for (int i = 0; i < 4; i++) {
            int slot = tid + 256 * i, r = slot >> 3, c4 = slot & 7;
            int pid = rows[r];
            ar[i] = (pid >= 0)
                ? *(const float4*)(x + (size_t)(pid >> 1) * DMODEL + s * BK + c4 * 4)
                : make_float4(0.f, 0.f, 0.f, 0.f);
        }
        #pragma unroll
        for (int i = 0; i < 2; i++) {
            int slot = tid + 256 * i, r = slot >> 3, c4 = slot & 7;
            w1r[i] = *(const float4*)(w1e + (size_t)r * DMODEL + s * BK + c4 * 4);
            w3r[i] = *(const float4*)(w3e + (size_t)r * DMODEL + s * BK + c4 * 4);
        }
    };

    auto STORE = [&](int p) {
        __nv_bfloat16* st = smem + p * G1_STAGE_ELEMS;
        #pragma unroll
        for (int i = 0; i < 4; i++) {
            int slot = tid + 256 * i, r = slot >> 3, c4 = slot & 7;
            uint32_t h0, l0, h1, l1;
            split2(ar[i].x, ar[i].y, h0, l0);
            split2(ar[i].z, ar[i].w, h1, l1);
            uint32_t off = r * SA + c4 * 4;
            *(uint2*)(st + off)            = make_uint2(h0, h1);
            *(uint2*)(st + 128 * SA + off) = make_uint2(l0, l1);
        }
        #pragma unroll
        for (int i = 0; i < 2; i++) {
            int slot = tid + 256 * i, r = slot >> 3, c4 = slot & 7;
            uint32_t off = r * SA + c4 * 4;
            uint32_t h0, l0, h1, l1;
            split2(w1r[i].x, w1r[i].y, h0, l0);
            split2(w1r[i].z, w1r[i].w, h1, l1);
            *(uint2*)(st + 256 * SA + off) = make_uint2(h0, h1);
            *(uint2*)(st + 320 * SA + off) = make_uint2(l0, l1);
            split2(w3r[i].x, w3r[i].y, h0, l0);
            split2(w3r[i].z, w3r[i].w, h1, l1);
            *(uint2*)(st + 384 * SA + off) = make_uint2(h0, h1);
            *(uint2*)(st + 448 * SA + off) = make_uint2(l0, l1);
        }
    };

    LOAD(0);
    const int NS = DMODEL / BK;   // 32
    for (int s = 0; s < NS; s++) {
        int p = s & 1;
        STORE(p);
        __syncthreads();
        if (s + 1 < NS) LOAD(s + 1);

        uint32_t stb = sb + p * (G1_STAGE_ELEMS * 2);
        #pragma unroll
        for (int ks = 0; ks < 2; ks++) {
            uint32_t kb = ks * 32;   // 16 bf16 = 32 bytes
            uint32_t ah[2][4], al[2][4];
            #pragma unroll
            for (int mt = 0; mt < 2; mt++) {
                ldsm4(ah[mt], stb + aoff + mt * (16 * SA2) + kb);
                ldsm4(al[mt], stb + 128 * SA2 + aoff + mt * (16 * SA2) + kb);
            }
            #pragma unroll
            for (int ntp = 0; ntp < 2; ntp++) {
                uint32_t b1h[4], b1l[4], b3h[4], b3l[4];
                uint32_t bo = boff + ntp * (16 * SA2) + kb;
                ldsm4(b1h, stb + 256 * SA2 + bo);
                ldsm4(b1l, stb + 320 * SA2 + bo);
                ldsm4(b3h, stb + 384 * SA2 + bo);
                ldsm4(b3l, stb + 448 * SA2 + bo);
                #pragma unroll
                for (int half = 0; half < 2; half++) {
                    int nt = ntp * 2 + half;
                    #pragma unroll
                    for (int mt = 0; mt < 2; mt++) {
                        mma_bf16(acc1[mt][nt], ah[mt], b1h[half * 2], b1h[half * 2 + 1]);
                        mma_bf16(acc1[mt][nt], ah[mt], b1l[half * 2], b1l[half * 2 + 1]);
                        mma_bf16(acc1[mt][nt], al[mt], b1h[half * 2], b1h[half * 2 + 1]);
                        mma_bf16(acc3[mt][nt], ah[mt], b3h[half * 2], b3h[half * 2 + 1]);
                        mma_bf16(acc3[mt][nt], ah[mt], b3l[half * 2], b3l[half * 2 + 1]);
                        mma_bf16(acc3[mt][nt], al[mt], b3h[half * 2], b3h[half * 2 + 1]);
                    }
                }
            }
        }
        __syncthreads();
    }

    // epilogue: silu(acc1) * acc3 -> g_H
    #pragma unroll
    for (int mt = 0; mt < 2; mt++) {
        int rl = warp_m * 32 + mt * 16 + g;
        int pid0 = rows[rl], pid1 = rows[rl + 8];
        #pragma unroll
        for (int nt = 0; nt < 4; nt++) {
            int col = n0 + warp_n * 32 + nt * 8 + 2 * t4;
            if (pid0 >= 0) {
                float z0 = acc1[mt][nt][0], z1 = acc1[mt][nt][1];
                float2 o;
                o.x = z0 / (1.f + __expf(-z0)) * acc3[mt][nt][0];
                o.y = z1 / (1.f + __expf(-z1)) * acc3[mt][nt][1];
                *(float2*)(g_H + (size_t)pid0 * DFF + col) = o;
            }
            if (pid1 >= 0) {
                float z2 = acc1[mt][nt][2], z3 = acc1[mt][nt][3];
                float2 o;
                o.x = z2 / (1.f + __expf(-z2)) * acc3[mt][nt][2];
                o.y = z3 / (1.f + __expf(-z3)) * acc3[mt][nt][3];
                *(float2*)(g_H + (size_t)pid1 * DFF + col) = o;
            }
        }
    }
}

// =====================  GEMM2: Y = Hg W2^T  ====================================
__global__ void __launch_bounds__(256) gemm2_tc(const float* __restrict__ w2) {
    int e = blockIdx.z;
    int c = g_cnt[e];
    int mt0 = blockIdx.x;
    if (mt0 * 128 >= c) return;
    int n0 = blockIdx.y * 64;

    extern __shared__ __align__(16) __nv_bfloat16 smem[];
    __shared__ int rows[128];

    int tid = threadIdx.x;
    if (tid < 128) {
        int pos = mt0 * 128 + tid;
        rows[tid] = (pos < c) ? g_list[e * TMAX + pos] : -1;
    }
    __syncthreads();

    const float* w2e = w2 + ((size_t)e * DMODEL + n0) * DFF;

    int lane = tid & 31, warp = tid >> 5;
    int warp_m = warp & 3, warp_n = warp >> 2;
    int g = lane >> 2, t4 = lane & 3;

    uint32_t sb = smem_u32(smem);
    uint32_t aoff = (uint32_t)((warp_m * 32 + (lane & 15)) * SA2 + ((lane >> 4) * 16));
    uint32_t boff = (uint32_t)((warp_n * 32 + (lane & 7) + ((lane & 16) ? 8 : 0)) * SA2 +
                               ((lane & 8) ? 16 : 0));

    float acc[2][4][4];
    #pragma unroll
    for (int i = 0; i < 2; i++)
        #pragma unroll
        for (int j = 0; j < 4; j++)
            #pragma unroll
            for (int k = 0; k < 4; k++) acc[i][j][k] = 0.f;

    float4 ar[4], wr[2];

    auto LOAD = [&](int s) {
        #pragma unroll
        for (int i = 0; i < 4; i++) {
            int slot = tid + 256 * i, r = slot >> 3, c4 = slot & 7;
            int pid = rows[r];
            ar[i] = (pid >= 0)
                ? *(const float4*)(g_H + (size_t)pid * DFF + s * BK + c4 * 4)
                : make_float4(0.f, 0.f, 0.f, 0.f);
        }
        #pragma unroll
        for (int i = 0; i < 2; i++) {
            int slot = tid + 256 * i, r = slot >> 3, c4 = slot & 7;
            wr[i] = *(const float4*)(w2e + (size_t)r * DFF + s * BK + c4 * 4);
        }
    };

    auto STORE = [&](int p) {
        __nv_bfloat16* st = smem + p * G2_STAGE_ELEMS;
        #pragma unroll
        for (int i = 0; i < 4; i++) {
            int slot = tid + 256 * i, r = slot >> 3, c4 = slot & 7;
            uint32_t h0, l0, h1, l1;
            split2(ar[i].x, ar[i].y, h0, l0);
            split2(ar[i].z, ar[i].w, h1, l1);
            uint32_t off = r * SA + c4 * 4;
            *(uint2*)(st + off)            = make_uint2(h0, h1);
            *(uint2*)(st + 128 * SA + off) = make_uint2(l0, l1);
        }
        #pragma unroll
        for (int i = 0; i < 2; i++) {
            int slot = tid + 256 * i, r = slot >> 3, c4 = slot & 7;
            uint32_t off = r * SA + c4 * 4;
            uint32_t h0, l0, h1, l1;
            split2(wr[i].x, wr[i].y, h0, l0);
            split2(wr[i].z, wr[i].w, h1, l1);
            *(uint2*)(st + 256 * SA + off) = make_uint2(h0, h1);
            *(uint2*)(st + 320 * SA + off) = make_uint2(l0, l1);
        }
    };

    LOAD(0);
    const int NS = DFF / BK;   // 64
    for (int s = 0; s < NS; s++) {
        int p = s & 1;
        STORE(p);
        __syncthreads();
        if (s + 1 < NS) LOAD(s + 1);

        uint32_t stb = sb + p * (G2_STAGE_ELEMS * 2);
        #pragma unroll
        for (int ks = 0; ks < 2; ks++) {
            uint32_t kb = ks * 32;
            uint32_t ah[2][4], al[2][4];
            #pragma unroll
            for (int mt = 0; mt < 2; mt++) {
                ldsm4(ah[mt], stb + aoff + mt * (16 * SA2) + kb);
                ldsm4(al[mt], stb + 128 * SA2 + aoff + mt * (16 * SA2) + kb);
            }
            #pragma unroll
            for (int ntp = 0; ntp < 2; ntp++) {
                uint32_t bh[4], bl[4];
                uint32_t bo = boff + ntp * (16 * SA2) + kb;
                ldsm4(bh, stb + 256 * SA2 + bo);
                ldsm4(bl, stb + 320 * SA2 + bo);
                #pragma unroll
                for (int half = 0; half < 2; half++) {
                    int nt = ntp * 2 + half;
                    #pragma unroll
                    for (int mt = 0; mt < 2; mt++) {
                        mma_bf16(acc[mt][nt], ah[mt], bh[half * 2], bh[half * 2 + 1]);
                        mma_bf16(acc[mt][nt], ah[mt], bl[half * 2], bl[half * 2 + 1]);
                        mma_bf16(acc[mt][nt], al[mt], bh[half * 2], bh[half * 2 + 1]);
                    }
                }
            }
        }
        __syncthreads();
    }

    #pragma unroll
    for (int mt = 0; mt < 2; mt++) {
        int rl = warp_m * 32 + mt * 16 + g;
        int pid0 = rows[rl], pid1 = rows[rl + 8];
        #pragma unroll
        for (int nt = 0; nt < 4; nt++) {
            int col = n0 + warp_n * 32 + nt * 8 + 2 * t4;
            if (pid0 >= 0)
                *(float2*)(g_Y + (size_t)pid0 * DMODEL + col) =
                    make_float2(acc[mt][nt][0], acc[mt][nt][1]);
            if (pid1 >= 0)
                *(float2*)(g_Y + (size_t)pid1 * DMODEL + col) =
                    make_float2(acc[mt][nt][2], acc[mt][nt][3]);
        }
    }
}

// ---------------- LayerNorm + coeff scale + scatter-add ------------------------
__global__ void __launch_bounds__(256) ln_kernel(
    const float* __restrict__ ln_g, const float* __restrict__ ln_b,
    float* __restrict__ out) {
    int pos = blockIdx.x;
    __shared__ float red[8];

    for (int e = 0; e < E_EXP; e++) {
        __syncthreads();
        if (pos >= g_cnt[e]) continue;
        int pid = g_list[e * TMAX + pos];
        float cf = g_coeff[e * TMAX + pos];
        int t = pid >> 1;
        const float* yr = g_Y + (size_t)pid * DMODEL;

        float v[4];
        float s = 0.f;
        #pragma unroll
        for (int i = 0; i < 4; i++) { v[i] = yr[threadIdx.x + i * 256]; s += v[i]; }
        int lane = threadIdx.x & 31, warp = threadIdx.x >> 5;
        #pragma unroll
        for (int o = 16; o; o >>= 1) s += __shfl_xor_sync(0xffffffffu, s, o);
        if (lane == 0) red[warp] = s;
        __syncthreads();
        float tot = 0.f;
        #pragma unroll
        for (int i = 0; i < 8; i++) tot += red[i];
        float mu = tot * (1.f / DMODEL);
        __syncthreads();

        float q = 0.f;
        #pragma unroll
        for (int i = 0; i < 4; i++) { float d = v[i] - mu; q += d * d; }
        #pragma unroll
        for (int o = 16; o; o >>= 1) q += __shfl_xor_sync(0xffffffffu, q, o);
        if (lane == 0) red[warp] = q;
        __syncthreads();
        float qt = 0.f;
        #pragma unroll
        for (int i = 0; i < 8; i++) qt += red[i];
        float rstd = rsqrtf(qt * (1.f / DMODEL) + LN_EPS);

        const float* g = ln_g + (size_t)e * DMODEL;
        const float* b = ln_b + (size_t)e * DMODEL;
        #pragma unroll
        for (int i = 0; i < 4; i++) {
            int col = threadIdx.x + i * 256;
            float yn = (v[i] - mu) * rstd * g[col] + b[col];
            atomicAdd(&out[(size_t)t * DMODEL + col], cf * yn);
        }
    }
}

// ---------------- launch --------------------------------------------------------
extern "C" void kernel_launch(void* const* d_in, const int* in_sizes, int n_in,
                              void* d_out, int out_size) {
    const float* x  = (const float*)d_in[0];
    const float* rw = (const float*)d_in[1];
    const float* rb = (const float*)d_in[2];
    const float* w1 = (const float*)d_in[3];
    const float* w2 = (const float*)d_in[4];
    const float* w3 = (const float*)d_in[5];
    const float* lg = (const float*)d_in[6];
    const float* lb = (const float*)d_in[7];
    float* out = (float*)d_out;

    int T = in_sizes[0] / DMODEL;   // 4096
    size_t n = (size_t)T * DMODEL;

    static bool attr_set = false;
    if (!attr_set) {
        cudaFuncSetAttribute(gemm1_tc, cudaFuncAttributeMaxDynamicSharedMemorySize, G1_SMEM);
        cudaFuncSetAttribute(gemm2_tc, cudaFuncAttributeMaxDynamicSharedMemorySize, G2_SMEM);
        attr_set = true;
    }

    zero_kernel<<<(unsigned)((n + 255) / 256), 256>>>(out, n);
    router_kernel<<<T, 128>>>(x, rw, rb);

    dim3 g1((T + 127) / 128, DFF / 64, E_EXP);
    gemm1_tc<<<g1, 256, G1_SMEM>>>(x, w1, w3);

    dim3 g2((T + 127) / 128, DMODEL / 64, E_EXP);
    gemm2_tc<<<g2, 256, G2_SMEM>>>(w2);

    ln_kernel<<<T, 256>>>(lg, lb, out);
}

// round 5
// speedup vs baseline: 2.9420x; 1.0092x over previous
#include <cuda_runtime.h>
#include <cuda_bf16.h>
#include <cstdint>

// Problem constants
#define E_EXP 16
#define DMODEL 1024
#define DFF 2048
#define TMAX 4096
#define LN_EPS 1e-5f

#define BK 32          // fp32 elements per K-chunk
#define SA 40          // smem row stride in bf16 elements (32 + 8 pad)
#define SA2 80         // stride in bytes

// ---------------- scratch (device globals) ------------------------------------
__device__ int   g_cnt[E_EXP];
__device__ int   g_list[E_EXP * TMAX];             // pid = token*2 + slot
__device__ int   g_tok_e[2 * TMAX];
__device__ float g_tok_c[2 * TMAX];
__device__ float g_Y[(size_t)2 * TMAX * DMODEL];   // [pid][D]

// pre-split bf16 hi/lo tensors
__device__ __align__(16) __nv_bfloat16 g_xh[(size_t)TMAX * DMODEL];
__device__ __align__(16) __nv_bfloat16 g_xl[(size_t)TMAX * DMODEL];
__device__ __align__(16) __nv_bfloat16 g_w1h[(size_t)E_EXP * DFF * DMODEL];
__device__ __align__(16) __nv_bfloat16 g_w1l[(size_t)E_EXP * DFF * DMODEL];
__device__ __align__(16) __nv_bfloat16 g_w3h[(size_t)E_EXP * DFF * DMODEL];
__device__ __align__(16) __nv_bfloat16 g_w3l[(size_t)E_EXP * DFF * DMODEL];
__device__ __align__(16) __nv_bfloat16 g_w2h[(size_t)E_EXP * DMODEL * DFF];
__device__ __align__(16) __nv_bfloat16 g_w2l[(size_t)E_EXP * DMODEL * DFF];
__device__ __align__(16) __nv_bfloat16 g_Hh[(size_t)2 * TMAX * DFF];
__device__ __align__(16) __nv_bfloat16 g_Hl[(size_t)2 * TMAX * DFF];

// ---------------- helpers -------------------------------------------------------
__device__ __forceinline__ uint32_t smem_u32(const void* p) {
    uint32_t a;
    asm("{ .reg .u64 t; cvta.to.shared.u64 t, %1; cvt.u32.u64 %0, t; }" : "=r"(a) : "l"(p));
    return a;
}

__device__ __forceinline__ void mma_bf16(float* c, const uint32_t* a,
                                         uint32_t b0, uint32_t b1) {
    asm volatile(
        "mma.sync.aligned.m16n8k16.row.col.f32.bf16.bf16.f32 "
        "{%0,%1,%2,%3}, {%4,%5,%6,%7}, {%8,%9}, {%0,%1,%2,%3};\n"
        : "+f"(c[0]), "+f"(c[1]), "+f"(c[2]), "+f"(c[3])
        : "r"(a[0]), "r"(a[1]), "r"(a[2]), "r"(a[3]), "r"(b0), "r"(b1));
}

__device__ __forceinline__ void ldsm4(uint32_t* r, uint32_t a) {
    asm volatile("ldmatrix.sync.aligned.m8n8.x4.shared.b16 {%0,%1,%2,%3}, [%4];"
        : "=r"(r[0]), "=r"(r[1]), "=r"(r[2]), "=r"(r[3]) : "r"(a));
}

__device__ __forceinline__ void split2(float x, float y, uint32_t& h, uint32_t& l) {
    __nv_bfloat16 hx = __float2bfloat16(x);
    __nv_bfloat16 hy = __float2bfloat16(y);
    __nv_bfloat16 lx = __float2bfloat16(x - __bfloat162float(hx));
    __nv_bfloat16 ly = __float2bfloat16(y - __bfloat162float(hy));
    h = (uint32_t)__bfloat16_as_ushort(hx) | ((uint32_t)__bfloat16_as_ushort(hy) << 16);
    l = (uint32_t)__bfloat16_as_ushort(lx) | ((uint32_t)__bfloat16_as_ushort(ly) << 16);
}

__device__ __forceinline__ void cpa16(uint32_t dst, const void* src, bool v) {
    int sz = v ? 16 : 0;
    asm volatile("cp.async.cg.shared.global [%0], [%1], 16, %2;\n"
                 :: "r"(dst), "l"(src), "r"(sz));
}
#define CP_COMMIT() asm volatile("cp.async.commit_group;\n" ::: "memory")
#define CP_WAIT(n)  asm volatile("cp.async.wait_group %0;\n" :: "n"(n) : "memory")

// ---------------- init + split --------------------------------------------------
__global__ void init_kernel() {
    if (threadIdx.x < E_EXP) g_cnt[threadIdx.x] = 0;
}

__global__ void split_kernel(const float4* __restrict__ src,
                             uint2* __restrict__ dh, uint2* __restrict__ dl,
                             int n4) {
    int i = blockIdx.x * blockDim.x + threadIdx.x;
    if (i >= n4) return;
    float4 v = src[i];
    uint32_t h0, l0, h1, l1;
    split2(v.x, v.y, h0, l0);
    split2(v.z, v.w, h1, l1);
    dh[i] = make_uint2(h0, h1);
    dl[i] = make_uint2(l0, l1);
}

// ---------------- router --------------------------------------------------------
__global__ void __launch_bounds__(128) router_kernel(
    const float* __restrict__ x, const float* __restrict__ rw,
    const float* __restrict__ rb) {
    int t = blockIdx.x;
    __shared__ float xs[DMODEL];
    __shared__ float logits[E_EXP];
    const float* xr = x + (size_t)t * DMODEL;
    for (int i = threadIdx.x; i < DMODEL; i += blockDim.x) xs[i] = xr[i];
    __syncthreads();

    int warp = threadIdx.x >> 5, lane = threadIdx.x & 31;
    for (int e = warp; e < E_EXP; e += 4) {
        const float* w = rw + (size_t)e * DMODEL;
        float s = 0.f;
        for (int k = lane; k < DMODEL; k += 32) s += xs[k] * w[k];
        #pragma unroll
        for (int o = 16; o; o >>= 1) s += __shfl_xor_sync(0xffffffffu, s, o);
        if (lane == 0) logits[e] = s + rb[e];
    }
    __syncthreads();

    if (threadIdx.x == 0) {
        float m = -1e30f;
        #pragma unroll
        for (int e = 0; e < E_EXP; e++) m = fmaxf(m, logits[e]);
        float p[E_EXP];
        #pragma unroll
        for (int e = 0; e < E_EXP; e++) p[e] = __expf(logits[e] - m);
        int e0 = 0;
        #pragma unroll
        for (int e = 1; e < E_EXP; e++) if (p[e] > p[e0]) e0 = e;
        int e1 = (e0 == 0) ? 1 : 0;
        #pragma unroll
        for (int e = 0; e < E_EXP; e++) {
            if (e == e0 || e == e1) continue;
            if (p[e] > p[e1]) e1 = e;
        }
        float s01 = p[e0] + p[e1];
        float c0 = p[e0] / s01, c1 = p[e1] / s01;
        int pos0 = atomicAdd(&g_cnt[e0], 1);
        g_list[e0 * TMAX + pos0] = t * 2 + 0;
        int pos1 = atomicAdd(&g_cnt[e1], 1);
        g_list[e1 * TMAX + pos1] = t * 2 + 1;
        g_tok_e[2 * t + 0] = e0; g_tok_c[2 * t + 0] = c0;
        g_tok_e[2 * t + 1] = e1; g_tok_c[2 * t + 1] = c1;
    }
}

// stage element offsets (rows of SA bf16):
//   gemm1: Ah 0(128) Al 128*SA | W1h 256*SA(64) W1l 320*SA | W3h 384*SA W3l 448*SA
//   gemm2: Ah 0(128) Al 128*SA | Wh  256*SA(64) Wl  320*SA
#define G1_STAGE_ELEMS (512 * SA)
#define G1_STAGE_BYTES (G1_STAGE_ELEMS * 2)
#define G1_SMEM (2 * G1_STAGE_BYTES)
#define G2_STAGE_ELEMS (384 * SA)
#define G2_STAGE_BYTES (G2_STAGE_ELEMS * 2)
#define G2_SMEM (2 * G2_STAGE_BYTES)

// =====================  GEMM1: H = silu(Xg W1^T) * (Xg W3^T)  ==================
__global__ void __launch_bounds__(256) gemm1_tc() {
    int e = blockIdx.z;
    int c = g_cnt[e];
    int mt0 = blockIdx.x;
    if (mt0 * 128 >= c) return;
    int n0 = blockIdx.y * 64;

    extern __shared__ __align__(16) __nv_bfloat16 smem[];
    __shared__ int rows[128];

    int tid = threadIdx.x;
    if (tid < 128) {
        int pos = mt0 * 128 + tid;
        rows[tid] = (pos < c) ? g_list[e * TMAX + pos] : -1;
    }
    __syncthreads();

    int lane = tid & 31, warp = tid >> 5;
    int warp_m = warp & 3, warp_n = warp >> 2;     // 4x2 warp grid
    int g = lane >> 2, t4 = lane & 3;

    uint32_t sb = smem_u32(smem);
    uint32_t aoff = (uint32_t)((warp_m * 32 + (lane & 15)) * SA2 + ((lane >> 4) * 16));
    uint32_t boff = (uint32_t)((warp_n * 32 + (lane & 7) + ((lane & 16) ? 8 : 0)) * SA2 +
                               ((lane & 8) ? 16 : 0));

    float acc1[2][4][4], acc3[2][4][4];
    #pragma unroll
    for (int i = 0; i < 2; i++)
        #pragma unroll
        for (int j = 0; j < 4; j++)
            #pragma unroll
            for (int k = 0; k < 4; k++) { acc1[i][j][k] = 0.f; acc3[i][j][k] = 0.f; }

    const size_t wbase = ((size_t)e * DFF + n0) * DMODEL;

    auto ISSUE = [&](int s) {
        uint32_t stb = sb + (s & 1) * G1_STAGE_BYTES;
        // A: 128 rows x 4 groups x {hi,lo} = 1024 copies
        #pragma unroll
        for (int i = 0; i < 4; i++) {
            int idx = tid + 256 * i;
            int r = idx >> 3, sub = idx & 7, grp = sub & 3, hf = sub >> 2;
            int pid = rows[r];
            const __nv_bfloat16* base = hf ? g_xl : g_xh;
            const void* sp = (pid >= 0)
                ? (const void*)(base + (size_t)(pid >> 1) * DMODEL + s * BK + grp * 8)
                : (const void*)base;
            uint32_t dst = stb + (uint32_t)((hf * 128 + r) * SA + grp * 8) * 2;
            cpa16(dst, sp, pid >= 0);
        }
        // W1: 64 rows x 4 x {hi,lo} = 512 copies
        #pragma unroll
        for (int i = 0; i < 2; i++) {
            int idx = tid + 256 * i;
            int hf = idx >> 8, rem = idx & 255, r = rem >> 2, grp = rem & 3;
            const __nv_bfloat16* base = hf ? g_w1l : g_w1h;
            const void* sp = base + wbase + (size_t)r * DMODEL + s * BK + grp * 8;
            uint32_t dst = stb + (uint32_t)((256 + hf * 64 + r) * SA + grp * 8) * 2;
            cpa16(dst, sp, true);
        }
        // W3: 512 copies
        #pragma unroll
        for (int i = 0; i < 2; i++) {
            int idx = tid + 256 * i;
            int hf = idx >> 8, rem = idx & 255, r = rem >> 2, grp = rem & 3;
            const __nv_bfloat16* base = hf ? g_w3l : g_w3h;
            const void* sp = base + wbase + (size_t)r * DMODEL + s * BK + grp * 8;
            uint32_t dst = stb + (uint32_t)((384 + hf * 64 + r) * SA + grp * 8) * 2;
            cpa16(dst, sp, true);
        }
    };

    const int NS = DMODEL / BK;   // 32
    ISSUE(0); CP_COMMIT();
    for (int s = 0; s < NS; s++) {
        if (s + 1 < NS) { ISSUE(s + 1); CP_COMMIT(); CP_WAIT(1); }
        else            { CP_WAIT(0); }
        __syncthreads();

        uint32_t stb = sb + (s & 1) * G1_STAGE_BYTES;
        #pragma unroll
        for (int ks = 0; ks < 2; ks++) {
            uint32_t kb = ks * 32;   // 16 bf16 = 32 bytes
            uint32_t ah[2][4], al[2][4];
            #pragma unroll
            for (int mt = 0; mt < 2; mt++) {
                ldsm4(ah[mt], stb + aoff + mt * (16 * SA2) + kb);
                ldsm4(al[mt], stb + 128 * SA2 + aoff + mt * (16 * SA2) + kb);
            }
            #pragma unroll
            for (int ntp = 0; ntp < 2; ntp++) {
                uint32_t b1h[4], b1l[4], b3h[4], b3l[4];
                uint32_t bo = boff + ntp * (16 * SA2) + kb;
                ldsm4(b1h, stb + 256 * SA2 + bo);
                ldsm4(b1l, stb + 320 * SA2 + bo);
                ldsm4(b3h, stb + 384 * SA2 + bo);
                ldsm4(b3l, stb + 448 * SA2 + bo);
                #pragma unroll
                for (int half = 0; half < 2; half++) {
                    int nt = ntp * 2 + half;
                    #pragma unroll
                    for (int mt = 0; mt < 2; mt++) {
                        mma_bf16(acc1[mt][nt], ah[mt], b1h[half * 2], b1h[half * 2 + 1]);
                        mma_bf16(acc1[mt][nt], ah[mt], b1l[half * 2], b1l[half * 2 + 1]);
                        mma_bf16(acc1[mt][nt], al[mt], b1h[half * 2], b1h[half * 2 + 1]);
                        mma_bf16(acc3[mt][nt], ah[mt], b3h[half * 2], b3h[half * 2 + 1]);
                        mma_bf16(acc3[mt][nt], ah[mt], b3l[half * 2], b3l[half * 2 + 1]);
                        mma_bf16(acc3[mt][nt], al[mt], b3h[half * 2], b3h[half * 2 + 1]);
                    }
                }
            }
        }
        __syncthreads();
    }

    // epilogue: silu(acc1) * acc3 -> split -> g_Hh / g_Hl
    #pragma unroll
    for (int mt = 0; mt < 2; mt++) {
        int rl = warp_m * 32 + mt * 16 + g;
        int pid0 = rows[rl], pid1 = rows[rl + 8];
        #pragma unroll
        for (int nt = 0; nt < 4; nt++) {
            int col = n0 + warp_n * 32 + nt * 8 + 2 * t4;
            if (pid0 >= 0) {
                float z0 = acc1[mt][nt][0], z1 = acc1[mt][nt][1];
                float o0 = z0 / (1.f + __expf(-z0)) * acc3[mt][nt][0];
                float o1 = z1 / (1.f + __expf(-z1)) * acc3[mt][nt][1];
                uint32_t h, l;
                split2(o0, o1, h, l);
                *(uint32_t*)(g_Hh + (size_t)pid0 * DFF + col) = h;
                *(uint32_t*)(g_Hl + (size_t)pid0 * DFF + col) = l;
            }
            if (pid1 >= 0) {
                float z2 = acc1[mt][nt][2], z3 = acc1[mt][nt][3];
                float o2 = z2 / (1.f + __expf(-z2)) * acc3[mt][nt][2];
                float o3 = z3 / (1.f + __expf(-z3)) * acc3[mt][nt][3];
                uint32_t h, l;
                split2(o2, o3, h, l);
                *(uint32_t*)(g_Hh + (size_t)pid1 * DFF + col) = h;
                *(uint32_t*)(g_Hl + (size_t)pid1 * DFF + col) = l;
            }
        }
    }
}

// =====================  GEMM2: Y = Hg W2^T  ====================================
__global__ void __launch_bounds__(256) gemm2_tc() {
    int e = blockIdx.z;
    int c = g_cnt[e];
    int mt0 = blockIdx.x;
    if (mt0 * 128 >= c) return;
    int n0 = blockIdx.y * 64;

    extern __shared__ __align__(16) __nv_bfloat16 smem[];
    __shared__ int rows[128];

    int tid = threadIdx.x;
    if (tid < 128) {
        int pos = mt0 * 128 + tid;
        rows[tid] = (pos < c) ? g_list[e * TMAX + pos] : -1;
    }
    __syncthreads();

    int lane = tid & 31, warp = tid >> 5;
    int warp_m = warp & 3, warp_n = warp >> 2;
    int g = lane >> 2, t4 = lane & 3;

    uint32_t sb = smem_u32(smem);
    uint32_t aoff = (uint32_t)((warp_m * 32 + (lane & 15)) * SA2 + ((lane >> 4) * 16));
    uint32_t boff = (uint32_t)((warp_n * 32 + (lane & 7) + ((lane & 16) ? 8 : 0)) * SA2 +
                               ((lane & 8) ? 16 : 0));

    float acc[2][4][4];
    #pragma unroll
    for (int i = 0; i < 2; i++)
        #pragma unroll
        for (int j = 0; j < 4; j++)
            #pragma unroll
            for (int k = 0; k < 4; k++) acc[i][j][k] = 0.f;

    const size_t wbase = ((size_t)e * DMODEL + n0) * DFF;

    auto ISSUE = [&](int s) {
        uint32_t stb = sb + (s & 1) * G2_STAGE_BYTES;
        // A (H rows): 1024 copies
        #pragma unroll
        for (int i = 0; i < 4; i++) {
            int idx = tid + 256 * i;
            int r = idx >> 3, sub = idx & 7, grp = sub & 3, hf = sub >> 2;
            int pid = rows[r];
            const __nv_bfloat16* base = hf ? g_Hl : g_Hh;
            const void* sp = (pid >= 0)
                ? (const void*)(base + (size_t)pid * DFF + s * BK + grp * 8)
                : (const void*)base;
            uint32_t dst = stb + (uint32_t)((hf * 128 + r) * SA + grp * 8) * 2;
            cpa16(dst, sp, pid >= 0);
        }
        // W2: 512 copies
        #pragma unroll
        for (int i = 0; i < 2; i++) {
            int idx = tid + 256 * i;
            int hf = idx >> 8, rem = idx & 255, r = rem >> 2, grp = rem & 3;
            const __nv_bfloat16* base = hf ? g_w2l : g_w2h;
            const void* sp = base + wbase + (size_t)r * DFF + s * BK + grp * 8;
            uint32_t dst = stb + (uint32_t)((256 + hf * 64 + r) * SA + grp * 8) * 2;
            cpa16(dst, sp, true);
        }
    };

    const int NS = DFF / BK;   // 64
    ISSUE(0); CP_COMMIT();
    for (int s = 0; s < NS; s++) {
        if (s + 1 < NS) { ISSUE(s + 1); CP_COMMIT(); CP_WAIT(1); }
        else            { CP_WAIT(0); }
        __syncthreads();

        uint32_t stb = sb + (s & 1) * G2_STAGE_BYTES;
        #pragma unroll
        for (int ks = 0; ks < 2; ks++) {
            uint32_t kb = ks * 32;
            uint32_t ah[2][4], al[2][4];
            #pragma unroll
            for (int mt = 0; mt < 2; mt++) {
                ldsm4(ah[mt], stb + aoff + mt * (16 * SA2) + kb);
                ldsm4(al[mt], stb + 128 * SA2 + aoff + mt * (16 * SA2) + kb);
            }
            #pragma unroll
            for (int ntp = 0; ntp < 2; ntp++) {
                uint32_t bh[4], bl[4];
                uint32_t bo = boff + ntp * (16 * SA2) + kb;
                ldsm4(bh, stb + 256 * SA2 + bo);
                ldsm4(bl, stb + 320 * SA2 + bo);
                #pragma unroll
                for (int half = 0; half < 2; half++) {
                    int nt = ntp * 2 + half;
                    #pragma unroll
                    for (int mt = 0; mt < 2; mt++) {
                        mma_bf16(acc[mt][nt], ah[mt], bh[half * 2], bh[half * 2 + 1]);
                        mma_bf16(acc[mt][nt], ah[mt], bl[half * 2], bl[half * 2 + 1]);
                        mma_bf16(acc[mt][nt], al[mt], bh[half * 2], bh[half * 2 + 1]);
                    }
                }
            }
        }
        __syncthreads();
    }

    #pragma unroll
    for (int mt = 0; mt < 2; mt++) {
        int rl = warp_m * 32 + mt * 16 + g;
        int pid0 = rows[rl], pid1 = rows[rl + 8];
        #pragma unroll
        for (int nt = 0; nt < 4; nt++) {
            int col = n0 + warp_n * 32 + nt * 8 + 2 * t4;
            if (pid0 >= 0)
                *(float2*)(g_Y + (size_t)pid0 * DMODEL + col) =
                    make_float2(acc[mt][nt][0], acc[mt][nt][1]);
            if (pid1 >= 0)
                *(float2*)(g_Y + (size_t)pid1 * DMODEL + col) =
                    make_float2(acc[mt][nt][2], acc[mt][nt][3]);
        }
    }
}

// ---------------- per-token dual LayerNorm + combine ---------------------------
__global__ void __launch_bounds__(256) ln2_kernel(
    const float* __restrict__ ln_g, const float* __restrict__ ln_b,
    float* __restrict__ out) {
    int t = blockIdx.x;
    int e0 = g_tok_e[2 * t], e1 = g_tok_e[2 * t + 1];
    float c0 = g_tok_c[2 * t], c1 = g_tok_c[2 * t + 1];
    const float* y0 = g_Y + (size_t)(2 * t) * DMODEL;
    const float* y1 = g_Y + (size_t)(2 * t + 1) * DMODEL;

    __shared__ float red[16];
    int lane = threadIdx.x & 31, warp = threadIdx.x >> 5;

    float v0[4], v1[4];
    float s0 = 0.f, s1 = 0.f;
    #pragma unroll
    for (int i = 0; i < 4; i++) {
        int col = threadIdx.x + i * 256;
        v0[i] = y0[col]; s0 += v0[i];
        v1[i] = y1[col]; s1 += v1[i];
    }
    #pragma unroll
    for (int o = 16; o; o >>= 1) {
        s0 += __shfl_xor_sync(0xffffffffu, s0, o);
        s1 += __shfl_xor_sync(0xffffffffu, s1, o);
    }
    if (lane == 0) { red[warp] = s0; red[8 + warp] = s1; }
    __syncthreads();
    float m0 = 0.f, m1 = 0.f;
    #pragma unroll
    for (int i = 0; i < 8; i++) { m0 += red[i]; m1 += red[8 + i]; }
    float mu0 = m0 * (1.f / DMODEL), mu1 = m1 * (1.f / DMODEL);
    __syncthreads();

    float q0 = 0.f, q1 = 0.f;
    #pragma unroll
    for (int i = 0; i < 4; i++) {
        float d0 = v0[i] - mu0; q0 += d0 * d0;
        float d1 = v1[i] - mu1; q1 += d1 * d1;
    }
    #pragma unroll
    for (int o = 16; o; o >>= 1) {
        q0 += __shfl_xor_sync(0xffffffffu, q0, o);
        q1 += __shfl_xor_sync(0xffffffffu, q1, o);
    }
    if (lane == 0) { red[warp] = q0; red[8 + warp] = q1; }
    __syncthreads();
    float t0 = 0.f, t1 = 0.f;
    #pragma unroll
    for (int i = 0; i < 8; i++) { t0 += red[i]; t1 += red[8 + i]; }
    float rstd0 = rsqrtf(t0 * (1.f / DMODEL) + LN_EPS);
    float rstd1 = rsqrtf(t1 * (1.f / DMODEL) + LN_EPS);

    const float* ga = ln_g + (size_t)e0 * DMODEL;
    const float* ba = ln_b + (size_t)e0 * DMODEL;
    const float* gb = ln_g + (size_t)e1 * DMODEL;
    const float* bb = ln_b + (size_t)e1 * DMODEL;
    #pragma unroll
    for (int i = 0; i < 4; i++) {
        int col = threadIdx.x + i * 256;
        float yn0 = (v0[i] - mu0) * rstd0 * ga[col] + ba[col];
        float yn1 = (v1[i] - mu1) * rstd1 * gb[col] + bb[col];
        out[(size_t)t * DMODEL + col] = c0 * yn0 + c1 * yn1;
    }
}

// ---------------- launch --------------------------------------------------------
extern "C" void kernel_launch(void* const* d_in, const int* in_sizes, int n_in,
                              void* d_out, int out_size) {
    const float* x  = (const float*)d_in[0];
    const float* rw = (const float*)d_in[1];
    const float* rb = (const float*)d_in[2];
    const float* w1 = (const float*)d_in[3];
    const float* w2 = (const float*)d_in[4];
    const float* w3 = (const float*)d_in[5];
    const float* lg = (const float*)d_in[6];
    const float* lb = (const float*)d_in[7];
    float* out = (float*)d_out;

    int T = in_sizes[0] / DMODEL;   // 4096

    cudaFuncSetAttribute(gemm1_tc, cudaFuncAttributeMaxDynamicSharedMemorySize, G1_SMEM);
    cudaFuncSetAttribute(gemm2_tc, cudaFuncAttributeMaxDynamicSharedMemorySize, G2_SMEM);

    init_kernel<<<1, 32>>>();

    // pre-split weights + x to bf16 hi/lo
    {
        __nv_bfloat16 *w1h, *w1l, *w3h, *w3l, *w2h, *w2l, *xh, *xl;
        cudaGetSymbolAddress((void**)&w1h, g_w1h);
        cudaGetSymbolAddress((void**)&w1l, g_w1l);
        cudaGetSymbolAddress((void**)&w3h, g_w3h);
        cudaGetSymbolAddress((void**)&w3l, g_w3l);
        cudaGetSymbolAddress((void**)&w2h, g_w2h);
        cudaGetSymbolAddress((void**)&w2l, g_w2l);
        cudaGetSymbolAddress((void**)&xh,  g_xh);
        cudaGetSymbolAddress((void**)&xl,  g_xl);

        int nw4 = (int)((size_t)E_EXP * DFF * DMODEL / 4);   // 8388608
        int nx4 = (int)((size_t)T * DMODEL / 4);             // 1048576
        split_kernel<<<nw4 / 256, 256>>>((const float4*)w1, (uint2*)w1h, (uint2*)w1l, nw4);
        split_kernel<<<nw4 / 256, 256>>>((const float4*)w3, (uint2*)w3h, (uint2*)w3l, nw4);
        split_kernel<<<nw4 / 256, 256>>>((const float4*)w2, (uint2*)w2h, (uint2*)w2l, nw4);
        split_kernel<<<(nx4 + 255) / 256, 256>>>((const float4*)x, (uint2*)xh, (uint2*)xl, nx4);
    }

    router_kernel<<<T, 128>>>(x, rw, rb);

    dim3 g1((T + 127) / 128, DFF / 64, E_EXP);
    gemm1_tc<<<g1, 256, G1_SMEM>>>();

    dim3 g2((T + 127) / 128, DMODEL / 64, E_EXP);
    gemm2_tc<<<g2, 256, G2_SMEM>>>();

    ln2_kernel<<<T, 256>>>(lg, lb, out);
}

// round 6
// speedup vs baseline: 3.5185x; 1.1960x over previous
#include <cuda_runtime.h>
#include <cuda_bf16.h>
#include <cstdint>

// Problem constants
#define E_EXP 16
#define DMODEL 1024
#define DFF 2048
#define TMAX 4096
#define LN_EPS 1e-5f

#define BK 32          // fp32 elements per K-chunk
#define SA 40          // smem row stride in bf16 elements (32 + 8 pad)
#define SA2 80         // stride in bytes

// ---------------- scratch (device globals) ------------------------------------
__device__ int   g_cnt[E_EXP];
__device__ int   g_list[E_EXP * TMAX];             // pid = token*2 + slot
__device__ int   g_tok_e[2 * TMAX];
__device__ float g_tok_c[2 * TMAX];
__device__ float g_Y[(size_t)2 * TMAX * DMODEL];   // [pid][D]

// pre-split bf16 hi/lo tensors
__device__ __align__(16) __nv_bfloat16 g_xh[(size_t)TMAX * DMODEL];
__device__ __align__(16) __nv_bfloat16 g_xl[(size_t)TMAX * DMODEL];
__device__ __align__(16) __nv_bfloat16 g_w1h[(size_t)E_EXP * DFF * DMODEL];
__device__ __align__(16) __nv_bfloat16 g_w1l[(size_t)E_EXP * DFF * DMODEL];
__device__ __align__(16) __nv_bfloat16 g_w3h[(size_t)E_EXP * DFF * DMODEL];
__device__ __align__(16) __nv_bfloat16 g_w3l[(size_t)E_EXP * DFF * DMODEL];
__device__ __align__(16) __nv_bfloat16 g_w2h[(size_t)E_EXP * DMODEL * DFF];
__device__ __align__(16) __nv_bfloat16 g_w2l[(size_t)E_EXP * DMODEL * DFF];
__device__ __align__(16) __nv_bfloat16 g_Hh[(size_t)2 * TMAX * DFF];
__device__ __align__(16) __nv_bfloat16 g_Hl[(size_t)2 * TMAX * DFF];

// ---------------- helpers -------------------------------------------------------
__device__ __forceinline__ uint32_t smem_u32(const void* p) {
    uint32_t a;
    asm("{ .reg .u64 t; cvta.to.shared.u64 t, %1; cvt.u32.u64 %0, t; }" : "=r"(a) : "l"(p));
    return a;
}

__device__ __forceinline__ void mma_bf16(float* c, const uint32_t* a,
                                         uint32_t b0, uint32_t b1) {
    asm volatile(
        "mma.sync.aligned.m16n8k16.row.col.f32.bf16.bf16.f32 "
        "{%0,%1,%2,%3}, {%4,%5,%6,%7}, {%8,%9}, {%0,%1,%2,%3};\n"
        : "+f"(c[0]), "+f"(c[1]), "+f"(c[2]), "+f"(c[3])
        : "r"(a[0]), "r"(a[1]), "r"(a[2]), "r"(a[3]), "r"(b0), "r"(b1));
}

__device__ __forceinline__ void ldsm4(uint32_t* r, uint32_t a) {
    asm volatile("ldmatrix.sync.aligned.m8n8.x4.shared.b16 {%0,%1,%2,%3}, [%4];"
        : "=r"(r[0]), "=r"(r[1]), "=r"(r[2]), "=r"(r[3]) : "r"(a));
}

__device__ __forceinline__ void split2(float x, float y, uint32_t& h, uint32_t& l) {
    __nv_bfloat16 hx = __float2bfloat16(x);
    __nv_bfloat16 hy = __float2bfloat16(y);
    __nv_bfloat16 lx = __float2bfloat16(x - __bfloat162float(hx));
    __nv_bfloat16 ly = __float2bfloat16(y - __bfloat162float(hy));
    h = (uint32_t)__bfloat16_as_ushort(hx) | ((uint32_t)__bfloat16_as_ushort(hy) << 16);
    l = (uint32_t)__bfloat16_as_ushort(lx) | ((uint32_t)__bfloat16_as_ushort(ly) << 16);
}

__device__ __forceinline__ void cpa16(uint32_t dst, const void* src, bool v) {
    int sz = v ? 16 : 0;
    asm volatile("cp.async.cg.shared.global [%0], [%1], 16, %2;\n"
                 :: "r"(dst), "l"(src), "r"(sz));
}
#define CP_COMMIT() asm volatile("cp.async.commit_group;\n" ::: "memory")
#define CP_WAIT(n)  asm volatile("cp.async.wait_group %0;\n" :: "n"(n) : "memory")

// ---------------- init + split --------------------------------------------------
__global__ void init_kernel() {
    if (threadIdx.x < E_EXP) g_cnt[threadIdx.x] = 0;
}

__global__ void split_kernel(const float4* __restrict__ src,
                             uint2* __restrict__ dh, uint2* __restrict__ dl,
                             int n4) {
    int i = blockIdx.x * blockDim.x + threadIdx.x;
    if (i >= n4) return;
    float4 v = src[i];
    uint32_t h0, l0, h1, l1;
    split2(v.x, v.y, h0, l0);
    split2(v.z, v.w, h1, l1);
    dh[i] = make_uint2(h0, h1);
    dl[i] = make_uint2(l0, l1);
}

// ---------------- router --------------------------------------------------------
__global__ void __launch_bounds__(128) router_kernel(
    const float* __restrict__ x, const float* __restrict__ rw,
    const float* __restrict__ rb) {
    int t = blockIdx.x;
    __shared__ float xs[DMODEL];
    __shared__ float logits[E_EXP];
    const float* xr = x + (size_t)t * DMODEL;
    for (int i = threadIdx.x; i < DMODEL; i += blockDim.x) xs[i] = xr[i];
    __syncthreads();

    int warp = threadIdx.x >> 5, lane = threadIdx.x & 31;
    for (int e = warp; e < E_EXP; e += 4) {
        const float* w = rw + (size_t)e * DMODEL;
        float s = 0.f;
        for (int k = lane; k < DMODEL; k += 32) s += xs[k] * w[k];
        #pragma unroll
        for (int o = 16; o; o >>= 1) s += __shfl_xor_sync(0xffffffffu, s, o);
        if (lane == 0) logits[e] = s + rb[e];
    }
    __syncthreads();

    if (threadIdx.x == 0) {
        float m = -1e30f;
        #pragma unroll
        for (int e = 0; e < E_EXP; e++) m = fmaxf(m, logits[e]);
        float p[E_EXP];
        #pragma unroll
        for (int e = 0; e < E_EXP; e++) p[e] = __expf(logits[e] - m);
        int e0 = 0;
        #pragma unroll
        for (int e = 1; e < E_EXP; e++) if (p[e] > p[e0]) e0 = e;
        int e1 = (e0 == 0) ? 1 : 0;
        #pragma unroll
        for (int e = 0; e < E_EXP; e++) {
            if (e == e0 || e == e1) continue;
            if (p[e] > p[e1]) e1 = e;
        }
        float s01 = p[e0] + p[e1];
        float c0 = p[e0] / s01, c1 = p[e1] / s01;
        int pos0 = atomicAdd(&g_cnt[e0], 1);
        g_list[e0 * TMAX + pos0] = t * 2 + 0;
        int pos1 = atomicAdd(&g_cnt[e1], 1);
        g_list[e1 * TMAX + pos1] = t * 2 + 1;
        g_tok_e[2 * t + 0] = e0; g_tok_c[2 * t + 0] = c0;
        g_tok_e[2 * t + 1] = e1; g_tok_c[2 * t + 1] = c1;
    }
}

// stage element offsets (rows of SA bf16):
//   gemm1: Ah 0(128) Al 128*SA | W1h 256*SA(64) W1l 320*SA | W3h 384*SA W3l 448*SA
//   gemm2: Ah 0(128) Al 128*SA | Wh  256*SA(64) Wl  320*SA
#define G1_STAGE_ELEMS (512 * SA)
#define G1_STAGE_BYTES (G1_STAGE_ELEMS * 2)
#define G1_SMEM (2 * G1_STAGE_BYTES)
#define G2_STAGE_ELEMS (384 * SA)
#define G2_STAGE_BYTES (G2_STAGE_ELEMS * 2)
#define G2_SMEM (2 * G2_STAGE_BYTES)

// =====================  GEMM1: H = silu(Xg W1^T) * (Xg W3^T)  ==================
__global__ void __launch_bounds__(256, 2) gemm1_tc() {
    int e = blockIdx.z;
    int c = g_cnt[e];
    int mt0 = blockIdx.x;
    if (mt0 * 128 >= c) return;
    int n0 = blockIdx.y * 64;

    extern __shared__ __align__(16) __nv_bfloat16 smem[];
    __shared__ int rows[128];

    int tid = threadIdx.x;
    if (tid < 128) {
        int pos = mt0 * 128 + tid;
        rows[tid] = (pos < c) ? g_list[e * TMAX + pos] : -1;
    }
    __syncthreads();

    int lane = tid & 31, warp = tid >> 5;
    int warp_m = warp & 3, warp_n = warp >> 2;     // 4x2 warp grid
    int g = lane >> 2, t4 = lane & 3;

    uint32_t sb = smem_u32(smem);
    uint32_t aoff = (uint32_t)((warp_m * 32 + (lane & 15)) * SA2 + ((lane >> 4) * 16));
    uint32_t boff = (uint32_t)((warp_n * 32 + (lane & 7) + ((lane & 16) ? 8 : 0)) * SA2 +
                               ((lane & 8) ? 16 : 0));

    float acc1[2][4][4], acc3[2][4][4];
    #pragma unroll
    for (int i = 0; i < 2; i++)
        #pragma unroll
        for (int j = 0; j < 4; j++)
            #pragma unroll
            for (int k = 0; k < 4; k++) { acc1[i][j][k] = 0.f; acc3[i][j][k] = 0.f; }

    const size_t wbase = ((size_t)e * DFF + n0) * DMODEL;

    auto ISSUE = [&](int s) {
        uint32_t stb = sb + (s & 1) * G1_STAGE_BYTES;
        #pragma unroll
        for (int i = 0; i < 4; i++) {
            int idx = tid + 256 * i;
            int r = idx >> 3, sub = idx & 7, grp = sub & 3, hf = sub >> 2;
            int pid = rows[r];
            const __nv_bfloat16* base = hf ? g_xl : g_xh;
            const void* sp = (pid >= 0)
                ? (const void*)(base + (size_t)(pid >> 1) * DMODEL + s * BK + grp * 8)
                : (const void*)base;
            uint32_t dst = stb + (uint32_t)((hf * 128 + r) * SA + grp * 8) * 2;
            cpa16(dst, sp, pid >= 0);
        }
        #pragma unroll
        for (int i = 0; i < 2; i++) {
            int idx = tid + 256 * i;
            int hf = idx >> 8, rem = idx & 255, r = rem >> 2, grp = rem & 3;
            const __nv_bfloat16* base = hf ? g_w1l : g_w1h;
            const void* sp = base + wbase + (size_t)r * DMODEL + s * BK + grp * 8;
            uint32_t dst = stb + (uint32_t)((256 + hf * 64 + r) * SA + grp * 8) * 2;
            cpa16(dst, sp, true);
        }
        #pragma unroll
        for (int i = 0; i < 2; i++) {
            int idx = tid + 256 * i;
            int hf = idx >> 8, rem = idx & 255, r = rem >> 2, grp = rem & 3;
            const __nv_bfloat16* base = hf ? g_w3l : g_w3h;
            const void* sp = base + wbase + (size_t)r * DMODEL + s * BK + grp * 8;
            uint32_t dst = stb + (uint32_t)((384 + hf * 64 + r) * SA + grp * 8) * 2;
            cpa16(dst, sp, true);
        }
    };

    const int NS = DMODEL / BK;   // 32
    ISSUE(0); CP_COMMIT();
    for (int s = 0; s < NS; s++) {
        if (s + 1 < NS) { ISSUE(s + 1); CP_COMMIT(); CP_WAIT(1); }
        else            { CP_WAIT(0); }
        __syncthreads();

        uint32_t stb = sb + (s & 1) * G1_STAGE_BYTES;
        #pragma unroll
        for (int ks = 0; ks < 2; ks++) {
            uint32_t kb = ks * 32;
            uint32_t ah[2][4], al[2][4];
            #pragma unroll
            for (int mt = 0; mt < 2; mt++) {
                ldsm4(ah[mt], stb + aoff + mt * (16 * SA2) + kb);
                ldsm4(al[mt], stb + 128 * SA2 + aoff + mt * (16 * SA2) + kb);
            }
            #pragma unroll
            for (int ntp = 0; ntp < 2; ntp++) {
                uint32_t b1h[4], b1l[4], b3h[4], b3l[4];
                uint32_t bo = boff + ntp * (16 * SA2) + kb;
                ldsm4(b1h, stb + 256 * SA2 + bo);
                ldsm4(b1l, stb + 320 * SA2 + bo);
                ldsm4(b3h, stb + 384 * SA2 + bo);
                ldsm4(b3l, stb + 448 * SA2 + bo);
                #pragma unroll
                for (int half = 0; half < 2; half++) {
                    int nt = ntp * 2 + half;
                    #pragma unroll
                    for (int mt = 0; mt < 2; mt++) {
                        mma_bf16(acc1[mt][nt], ah[mt], b1h[half * 2], b1h[half * 2 + 1]);
                        mma_bf16(acc1[mt][nt], ah[mt], b1l[half * 2], b1l[half * 2 + 1]);
                        mma_bf16(acc1[mt][nt], al[mt], b1h[half * 2], b1h[half * 2 + 1]);
                        mma_bf16(acc3[mt][nt], ah[mt], b3h[half * 2], b3h[half * 2 + 1]);
                        mma_bf16(acc3[mt][nt], ah[mt], b3l[half * 2], b3l[half * 2 + 1]);
                        mma_bf16(acc3[mt][nt], al[mt], b3h[half * 2], b3h[half * 2 + 1]);
                    }
                }
            }
        }
        __syncthreads();
    }

    // epilogue: silu(acc1) * acc3 -> split -> g_Hh / g_Hl
    #pragma unroll
    for (int mt = 0; mt < 2; mt++) {
        int rl = warp_m * 32 + mt * 16 + g;
        int pid0 = rows[rl], pid1 = rows[rl + 8];
        #pragma unroll
        for (int nt = 0; nt < 4; nt++) {
            int col = n0 + warp_n * 32 + nt * 8 + 2 * t4;
            if (pid0 >= 0) {
                float z0 = acc1[mt][nt][0], z1 = acc1[mt][nt][1];
                float o0 = z0 / (1.f + __expf(-z0)) * acc3[mt][nt][0];
                float o1 = z1 / (1.f + __expf(-z1)) * acc3[mt][nt][1];
                uint32_t h, l;
                split2(o0, o1, h, l);
                *(uint32_t*)(g_Hh + (size_t)pid0 * DFF + col) = h;
                *(uint32_t*)(g_Hl + (size_t)pid0 * DFF + col) = l;
            }
            if (pid1 >= 0) {
                float z2 = acc1[mt][nt][2], z3 = acc1[mt][nt][3];
                float o2 = z2 / (1.f + __expf(-z2)) * acc3[mt][nt][2];
                float o3 = z3 / (1.f + __expf(-z3)) * acc3[mt][nt][3];
                uint32_t h, l;
                split2(o2, o3, h, l);
                *(uint32_t*)(g_Hh + (size_t)pid1 * DFF + col) = h;
                *(uint32_t*)(g_Hl + (size_t)pid1 * DFF + col) = l;
            }
        }
    }
}

// =====================  GEMM2: Y = Hg W2^T  ====================================
__global__ void __launch_bounds__(256, 2) gemm2_tc() {
    int e = blockIdx.z;
    int c = g_cnt[e];
    int mt0 = blockIdx.x;
    if (mt0 * 128 >= c) return;
    int n0 = blockIdx.y * 64;

    extern __shared__ __align__(16) __nv_bfloat16 smem[];
    __shared__ int rows[128];

    int tid = threadIdx.x;
    if (tid < 128) {
        int pos = mt0 * 128 + tid;
        rows[tid] = (pos < c) ? g_list[e * TMAX + pos] : -1;
    }
    __syncthreads();

    int lane = tid & 31, warp = tid >> 5;
    int warp_m = warp & 3, warp_n = warp >> 2;
    int g = lane >> 2, t4 = lane & 3;

    uint32_t sb = smem_u32(smem);
    uint32_t aoff = (uint32_t)((warp_m * 32 + (lane & 15)) * SA2 + ((lane >> 4) * 16));
    uint32_t boff = (uint32_t)((warp_n * 32 + (lane & 7) + ((lane & 16) ? 8 : 0)) * SA2 +
                               ((lane & 8) ? 16 : 0));

    float acc[2][4][4];
    #pragma unroll
    for (int i = 0; i < 2; i++)
        #pragma unroll
        for (int j = 0; j < 4; j++)
            #pragma unroll
            for (int k = 0; k < 4; k++) acc[i][j][k] = 0.f;

    const size_t wbase = ((size_t)e * DMODEL + n0) * DFF;

    auto ISSUE = [&](int s) {
        uint32_t stb = sb + (s & 1) * G2_STAGE_BYTES;
        #pragma unroll
        for (int i = 0; i < 4; i++) {
            int idx = tid + 256 * i;
            int r = idx >> 3, sub = idx & 7, grp = sub & 3, hf = sub >> 2;
            int pid = rows[r];
            const __nv_bfloat16* base = hf ? g_Hl : g_Hh;
            const void* sp = (pid >= 0)
                ? (const void*)(base + (size_t)pid * DFF + s * BK + grp * 8)
                : (const void*)base;
            uint32_t dst = stb + (uint32_t)((hf * 128 + r) * SA + grp * 8) * 2;
            cpa16(dst, sp, pid >= 0);
        }
        #pragma unroll
        for (int i = 0; i < 2; i++) {
            int idx = tid + 256 * i;
            int hf = idx >> 8, rem = idx & 255, r = rem >> 2, grp = rem & 3;
            const __nv_bfloat16* base = hf ? g_w2l : g_w2h;
            const void* sp = base + wbase + (size_t)r * DFF + s * BK + grp * 8;
            uint32_t dst = stb + (uint32_t)((256 + hf * 64 + r) * SA + grp * 8) * 2;
            cpa16(dst, sp, true);
        }
    };

    const int NS = DFF / BK;   // 64
    ISSUE(0); CP_COMMIT();
    for (int s = 0; s < NS; s++) {
        if (s + 1 < NS) { ISSUE(s + 1); CP_COMMIT(); CP_WAIT(1); }
        else            { CP_WAIT(0); }
        __syncthreads();

        uint32_t stb = sb + (s & 1) * G2_STAGE_BYTES;
        #pragma unroll
        for (int ks = 0; ks < 2; ks++) {
            uint32_t kb = ks * 32;
            uint32_t ah[2][4], al[2][4];
            #pragma unroll
            for (int mt = 0; mt < 2; mt++) {
                ldsm4(ah[mt], stb + aoff + mt * (16 * SA2) + kb);
                ldsm4(al[mt], stb + 128 * SA2 + aoff + mt * (16 * SA2) + kb);
            }
            #pragma unroll
            for (int ntp = 0; ntp < 2; ntp++) {
                uint32_t bh[4], bl[4];
                uint32_t bo = boff + ntp * (16 * SA2) + kb;
                ldsm4(bh, stb + 256 * SA2 + bo);
                ldsm4(bl, stb + 320 * SA2 + bo);
                #pragma unroll
                for (int half = 0; half < 2; half++) {
                    int nt = ntp * 2 + half;
                    #pragma unroll
                    for (int mt = 0; mt < 2; mt++) {
                        mma_bf16(acc[mt][nt], ah[mt], bh[half * 2], bh[half * 2 + 1]);
                        mma_bf16(acc[mt][nt], ah[mt], bl[half * 2], bl[half * 2 + 1]);
                        mma_bf16(acc[mt][nt], al[mt], bh[half * 2], bh[half * 2 + 1]);
                    }
                }
            }
        }
        __syncthreads();
    }

    #pragma unroll
    for (int mt = 0; mt < 2; mt++) {
        int rl = warp_m * 32 + mt * 16 + g;
        int pid0 = rows[rl], pid1 = rows[rl + 8];
        #pragma unroll
        for (int nt = 0; nt < 4; nt++) {
            int col = n0 + warp_n * 32 + nt * 8 + 2 * t4;
            if (pid0 >= 0)
                *(float2*)(g_Y + (size_t)pid0 * DMODEL + col) =
                    make_float2(acc[mt][nt][0], acc[mt][nt][1]);
            if (pid1 >= 0)
                *(float2*)(g_Y + (size_t)pid1 * DMODEL + col) =
                    make_float2(acc[mt][nt][2], acc[mt][nt][3]);
        }
    }
}

// ---------------- per-token dual LayerNorm + combine ---------------------------
__global__ void __launch_bounds__(256) ln2_kernel(
    const float* __restrict__ ln_g, const float* __restrict__ ln_b,
    float* __restrict__ out) {
    int t = blockIdx.x;
    int e0 = g_tok_e[2 * t], e1 = g_tok_e[2 * t + 1];
    float c0 = g_tok_c[2 * t], c1 = g_tok_c[2 * t + 1];
    const float* y0 = g_Y + (size_t)(2 * t) * DMODEL;
    const float* y1 = g_Y + (size_t)(2 * t + 1) * DMODEL;

    __shared__ float red[16];
    int lane = threadIdx.x & 31, warp = threadIdx.x >> 5;

    float v0[4], v1[4];
    float s0 = 0.f, s1 = 0.f;
    #pragma unroll
    for (int i = 0; i < 4; i++) {
        int col = threadIdx.x + i * 256;
        v0[i] = y0[col]; s0 += v0[i];
        v1[i] = y1[col]; s1 += v1[i];
    }
    #pragma unroll
    for (int o = 16; o; o >>= 1) {
        s0 += __shfl_xor_sync(0xffffffffu, s0, o);
        s1 += __shfl_xor_sync(0xffffffffu, s1, o);
    }
    if (lane == 0) { red[warp] = s0; red[8 + warp] = s1; }
    __syncthreads();
    float m0 = 0.f, m1 = 0.f;
    #pragma unroll
    for (int i = 0; i < 8; i++) { m0 += red[i]; m1 += red[8 + i]; }
    float mu0 = m0 * (1.f / DMODEL), mu1 = m1 * (1.f / DMODEL);
    __syncthreads();

    float q0 = 0.f, q1 = 0.f;
    #pragma unroll
    for (int i = 0; i < 4; i++) {
        float d0 = v0[i] - mu0; q0 += d0 * d0;
        float d1 = v1[i] - mu1; q1 += d1 * d1;
    }
    #pragma unroll
    for (int o = 16; o; o >>= 1) {
        q0 += __shfl_xor_sync(0xffffffffu, q0, o);
        q1 += __shfl_xor_sync(0xffffffffu, q1, o);
    }
    if (lane == 0) { red[warp] = q0; red[8 + warp] = q1; }
    __syncthreads();
    float t0 = 0.f, t1 = 0.f;
    #pragma unroll
    for (int i = 0; i < 8; i++) { t0 += red[i]; t1 += red[8 + i]; }
    float rstd0 = rsqrtf(t0 * (1.f / DMODEL) + LN_EPS);
    float rstd1 = rsqrtf(t1 * (1.f / DMODEL) + LN_EPS);

    const float* ga = ln_g + (size_t)e0 * DMODEL;
    const float* ba = ln_b + (size_t)e0 * DMODEL;
    const float* gb = ln_g + (size_t)e1 * DMODEL;
    const float* bb = ln_b + (size_t)e1 * DMODEL;
    #pragma unroll
    for (int i = 0; i < 4; i++) {
        int col = threadIdx.x + i * 256;
        float yn0 = (v0[i] - mu0) * rstd0 * ga[col] + ba[col];
        float yn1 = (v1[i] - mu1) * rstd1 * gb[col] + bb[col];
        out[(size_t)t * DMODEL + col] = c0 * yn0 + c1 * yn1;
    }
}

// ---------------- launch --------------------------------------------------------
extern "C" void kernel_launch(void* const* d_in, const int* in_sizes, int n_in,
                              void* d_out, int out_size) {
    const float* x  = (const float*)d_in[0];
    const float* rw = (const float*)d_in[1];
    const float* rb = (const float*)d_in[2];
    const float* w1 = (const float*)d_in[3];
    const float* w2 = (const float*)d_in[4];
    const float* w3 = (const float*)d_in[5];
    const float* lg = (const float*)d_in[6];
    const float* lb = (const float*)d_in[7];
    float* out = (float*)d_out;

    int T = in_sizes[0] / DMODEL;   // 4096

    cudaFuncSetAttribute(gemm1_tc, cudaFuncAttributeMaxDynamicSharedMemorySize, G1_SMEM);
    cudaFuncSetAttribute(gemm2_tc, cudaFuncAttributeMaxDynamicSharedMemorySize, G2_SMEM);
    cudaFuncSetAttribute(gemm1_tc, cudaFuncAttributePreferredSharedMemoryCarveout,
                         cudaSharedmemCarveoutMaxShared);
    cudaFuncSetAttribute(gemm2_tc, cudaFuncAttributePreferredSharedMemoryCarveout,
                         cudaSharedmemCarveoutMaxShared);

    init_kernel<<<1, 32>>>();

    // pre-split weights + x to bf16 hi/lo
    {
        __nv_bfloat16 *w1h, *w1l, *w3h, *w3l, *w2h, *w2l, *xh, *xl;
        cudaGetSymbolAddress((void**)&w1h, g_w1h);
        cudaGetSymbolAddress((void**)&w1l, g_w1l);
        cudaGetSymbolAddress((void**)&w3h, g_w3h);
        cudaGetSymbolAddress((void**)&w3l, g_w3l);
        cudaGetSymbolAddress((void**)&w2h, g_w2h);
        cudaGetSymbolAddress((void**)&w2l, g_w2l);
        cudaGetSymbolAddress((void**)&xh,  g_xh);
        cudaGetSymbolAddress((void**)&xl,  g_xl);

        int nw4 = (int)((size_t)E_EXP * DFF * DMODEL / 4);   // 8388608
        int nx4 = (int)((size_t)T * DMODEL / 4);             // 1048576
        split_kernel<<<nw4 / 256, 256>>>((const float4*)w1, (uint2*)w1h, (uint2*)w1l, nw4);
        split_kernel<<<nw4 / 256, 256>>>((const float4*)w3, (uint2*)w3h, (uint2*)w3l, nw4);
        split_kernel<<<nw4 / 256, 256>>>((const float4*)w2, (uint2*)w2h, (uint2*)w2l, nw4);
        split_kernel<<<(nx4 + 255) / 256, 256>>>((const float4*)x, (uint2*)xh, (uint2*)xl, nx4);
    }

    router_kernel<<<T, 128>>>(x, rw, rb);

    dim3 g1((T + 127) / 128, DFF / 64, E_EXP);
    gemm1_tc<<<g1, 256, G1_SMEM>>>();

    dim3 g2((T + 127) / 128, DMODEL / 64, E_EXP);
    gemm2_tc<<<g2, 256, G2_SMEM>>>();

    ln2_kernel<<<T, 256>>>(lg, lb, out);
}

// round 7
// speedup vs baseline: 3.9269x; 1.1161x over previous
#include <cuda_runtime.h>
#include <cuda_bf16.h>
#include <cstdint>

// Problem constants
#define E_EXP 16
#define DMODEL 1024
#define DFF 2048
#define TMAX 4096
#define LN_EPS 1e-5f

#define BK 32          // fp32 elements per K-chunk

// ---------------- scratch (device globals) ------------------------------------
__device__ int   g_cnt[E_EXP];
__device__ int   g_list[E_EXP * TMAX];             // pid = token*2 + slot
__device__ int   g_tok_e[2 * TMAX];
__device__ float g_tok_c[2 * TMAX];
__device__ float g_Y[(size_t)2 * TMAX * DMODEL];   // [pid][D]

// pre-split bf16 hi/lo tensors
__device__ __align__(16) __nv_bfloat16 g_xh[(size_t)TMAX * DMODEL];
__device__ __align__(16) __nv_bfloat16 g_xl[(size_t)TMAX * DMODEL];
__device__ __align__(16) __nv_bfloat16 g_w1h[(size_t)E_EXP * DFF * DMODEL];
__device__ __align__(16) __nv_bfloat16 g_w1l[(size_t)E_EXP * DFF * DMODEL];
__device__ __align__(16) __nv_bfloat16 g_w3h[(size_t)E_EXP * DFF * DMODEL];
__device__ __align__(16) __nv_bfloat16 g_w3l[(size_t)E_EXP * DFF * DMODEL];
__device__ __align__(16) __nv_bfloat16 g_w2h[(size_t)E_EXP * DMODEL * DFF];
__device__ __align__(16) __nv_bfloat16 g_w2l[(size_t)E_EXP * DMODEL * DFF];
__device__ __align__(16) __nv_bfloat16 g_Hh[(size_t)2 * TMAX * DFF];
__device__ __align__(16) __nv_bfloat16 g_Hl[(size_t)2 * TMAX * DFF];

// ---------------- helpers -------------------------------------------------------
__device__ __forceinline__ uint32_t smem_u32(const void* p) {
    uint32_t a;
    asm("{ .reg .u64 t; cvta.to.shared.u64 t, %1; cvt.u32.u64 %0, t; }" : "=r"(a) : "l"(p));
    return a;
}

__device__ __forceinline__ void mma_bf16(float* c, const uint32_t* a,
                                         uint32_t b0, uint32_t b1) {
    asm volatile(
        "mma.sync.aligned.m16n8k16.row.col.f32.bf16.bf16.f32 "
        "{%0,%1,%2,%3}, {%4,%5,%6,%7}, {%8,%9}, {%0,%1,%2,%3};\n"
        : "+f"(c[0]), "+f"(c[1]), "+f"(c[2]), "+f"(c[3])
        : "r"(a[0]), "r"(a[1]), "r"(a[2]), "r"(a[3]), "r"(b0), "r"(b1));
}

__device__ __forceinline__ void ldsm4(uint32_t* r, uint32_t a) {
    asm volatile("ldmatrix.sync.aligned.m8n8.x4.shared.b16 {%0,%1,%2,%3}, [%4];"
        : "=r"(r[0]), "=r"(r[1]), "=r"(r[2]), "=r"(r[3]) : "r"(a));
}

__device__ __forceinline__ void split2(float x, float y, uint32_t& h, uint32_t& l) {
    __nv_bfloat16 hx = __float2bfloat16(x);
    __nv_bfloat16 hy = __float2bfloat16(y);
    __nv_bfloat16 lx = __float2bfloat16(x - __bfloat162float(hx));
    __nv_bfloat16 ly = __float2bfloat16(y - __bfloat162float(hy));
    h = (uint32_t)__bfloat16_as_ushort(hx) | ((uint32_t)__bfloat16_as_ushort(hy) << 16);
    l = (uint32_t)__bfloat16_as_ushort(lx) | ((uint32_t)__bfloat16_as_ushort(ly) << 16);
}

__device__ __forceinline__ void cpa16(uint32_t dst, const void* src, bool v) {
    int sz = v ? 16 : 0;
    asm volatile("cp.async.cg.shared.global [%0], [%1], 16, %2;\n"
                 :: "r"(dst), "l"(src), "r"(sz));
}
#define CP_COMMIT() asm volatile("cp.async.commit_group;\n" ::: "memory")
#define CP_WAIT(n)  asm volatile("cp.async.wait_group %0;\n" :: "n"(n) : "memory")

// physical smem offset of logical (row, 16B-unit) under XOR swizzle, 64B rows
__device__ __forceinline__ uint32_t swz(int row, int unit) {
    return (uint32_t)(row * 64 + ((unit ^ ((row & 7) >> 1)) << 4));
}

// ---------------- init + split --------------------------------------------------
__global__ void init_kernel() {
    if (threadIdx.x < E_EXP) g_cnt[threadIdx.x] = 0;
}

__global__ void split_kernel(const float4* __restrict__ src,
                             uint2* __restrict__ dh, uint2* __restrict__ dl,
                             int n4) {
    int i = blockIdx.x * blockDim.x + threadIdx.x;
    if (i >= n4) return;
    float4 v = src[i];
    uint32_t h0, l0, h1, l1;
    split2(v.x, v.y, h0, l0);
    split2(v.z, v.w, h1, l1);
    dh[i] = make_uint2(h0, h1);
    dl[i] = make_uint2(l0, l1);
}

// ---------------- router --------------------------------------------------------
__global__ void __launch_bounds__(128) router_kernel(
    const float* __restrict__ x, const float* __restrict__ rw,
    const float* __restrict__ rb) {
    int t = blockIdx.x;
    __shared__ float xs[DMODEL];
    __shared__ float logits[E_EXP];
    const float* xr = x + (size_t)t * DMODEL;
    for (int i = threadIdx.x; i < DMODEL; i += blockDim.x) xs[i] = xr[i];
    __syncthreads();

    int warp = threadIdx.x >> 5, lane = threadIdx.x & 31;
    for (int e = warp; e < E_EXP; e += 4) {
        const float* w = rw + (size_t)e * DMODEL;
        float s = 0.f;
        for (int k = lane; k < DMODEL; k += 32) s += xs[k] * w[k];
        #pragma unroll
        for (int o = 16; o; o >>= 1) s += __shfl_xor_sync(0xffffffffu, s, o);
        if (lane == 0) logits[e] = s + rb[e];
    }
    __syncthreads();

    if (threadIdx.x == 0) {
        float m = -1e30f;
        #pragma unroll
        for (int e = 0; e < E_EXP; e++) m = fmaxf(m, logits[e]);
        float p[E_EXP];
        #pragma unroll
        for (int e = 0; e < E_EXP; e++) p[e] = __expf(logits[e] - m);
        int e0 = 0;
        #pragma unroll
        for (int e = 1; e < E_EXP; e++) if (p[e] > p[e0]) e0 = e;
        int e1 = (e0 == 0) ? 1 : 0;
        #pragma unroll
        for (int e = 0; e < E_EXP; e++) {
            if (e == e0 || e == e1) continue;
            if (p[e] > p[e1]) e1 = e;
        }
        float s01 = p[e0] + p[e1];
        float c0 = p[e0] / s01, c1 = p[e1] / s01;
        int pos0 = atomicAdd(&g_cnt[e0], 1);
        g_list[e0 * TMAX + pos0] = t * 2 + 0;
        int pos1 = atomicAdd(&g_cnt[e1], 1);
        g_list[e1 * TMAX + pos1] = t * 2 + 1;
        g_tok_e[2 * t + 0] = e0; g_tok_c[2 * t + 0] = c0;
        g_tok_e[2 * t + 1] = e1; g_tok_c[2 * t + 1] = c1;
    }
}

// stage byte layout (64B rows, swizzled):
//   gemm1: Ah 0 (128 rows) | Al 8192 | W1h 16384 (64) | W1l 20480 | W3h 24576 | W3l 28672
//   gemm2: Ah 0 | Al 8192 | Wh 16384 | Wl 20480
#define G1_STG 32768
#define G1_SMEM (3 * G1_STG)
#define G2_STG 24576
#define G2_SMEM (3 * G2_STG)

// =====================  GEMM1: H = silu(Xg W1^T) * (Xg W3^T)  ==================
__global__ void __launch_bounds__(256, 2) gemm1_tc() {
    int e = blockIdx.z;
    int c = g_cnt[e];
    int mt0 = blockIdx.x;
    if (mt0 * 128 >= c) return;
    int n0 = blockIdx.y * 64;

    extern __shared__ __align__(128) char smem[];
    __shared__ int rows[128];

    int tid = threadIdx.x;
    if (tid < 128) {
        int pos = mt0 * 128 + tid;
        rows[tid] = (pos < c) ? g_list[e * TMAX + pos] : -1;
    }
    __syncthreads();

    int lane = tid & 31, warp = tid >> 5;
    int warp_m = warp & 3, warp_n = warp >> 2;     // 4x2 warp grid
    int g = lane >> 2, t4 = lane & 3;

    uint32_t sb = smem_u32(smem);
    // ldmatrix per-lane logical coords
    int rowA0 = warp_m * 32 + (lane & 15);         // + mt*16
    int u0a = lane >> 4;                            // 0/1
    int rowB0 = warp_n * 32 + (lane & 7) + ((lane & 16) ? 8 : 0);  // + ntp*16
    int u0b = (lane >> 3) & 1;

    float acc1[2][4][4], acc3[2][4][4];
    #pragma unroll
    for (int i = 0; i < 2; i++)
        #pragma unroll
        for (int j = 0; j < 4; j++)
            #pragma unroll
            for (int k = 0; k < 4; k++) { acc1[i][j][k] = 0.f; acc3[i][j][k] = 0.f; }

    const size_t wbase = ((size_t)e * DFF + n0) * DMODEL;

    auto ISSUE = [&](int s) {
        uint32_t stb = sb + (uint32_t)(s % 3) * G1_STG;
        #pragma unroll
        for (int i = 0; i < 4; i++) {
            int idx = tid + 256 * i;
            int r = idx >> 3, sub = idx & 7, grp = sub & 3, hf = sub >> 2;
            int pid = rows[r];
            const __nv_bfloat16* base = hf ? g_xl : g_xh;
            const void* sp = (pid >= 0)
                ? (const void*)(base + (size_t)(pid >> 1) * DMODEL + s * BK + grp * 8)
                : (const void*)base;
            cpa16(stb + hf * 8192 + swz(r, grp), sp, pid >= 0);
        }
        #pragma unroll
        for (int i = 0; i < 2; i++) {
            int idx = tid + 256 * i;
            int hf = idx >> 8, rem = idx & 255, r = rem >> 2, grp = rem & 3;
            const __nv_bfloat16* base = hf ? g_w1l : g_w1h;
            const void* sp = base + wbase + (size_t)r * DMODEL + s * BK + grp * 8;
            cpa16(stb + 16384 + hf * 4096 + swz(r, grp), sp, true);
        }
        #pragma unroll
        for (int i = 0; i < 2; i++) {
            int idx = tid + 256 * i;
            int hf = idx >> 8, rem = idx & 255, r = rem >> 2, grp = rem & 3;
            const __nv_bfloat16* base = hf ? g_w3l : g_w3h;
            const void* sp = base + wbase + (size_t)r * DMODEL + s * BK + grp * 8;
            cpa16(stb + 24576 + hf * 4096 + swz(r, grp), sp, true);
        }
    };

    const int NS = DMODEL / BK;   // 32
    ISSUE(0); CP_COMMIT();
    ISSUE(1); CP_COMMIT();
    for (int s = 0; s < NS; s++) {
        CP_WAIT(1);
        __syncthreads();
        if (s + 2 < NS) ISSUE(s + 2);
        CP_COMMIT();

        uint32_t stb = sb + (uint32_t)(s % 3) * G1_STG;
        #pragma unroll
        for (int ks = 0; ks < 2; ks++) {
            uint32_t ah[2][4], al[2][4];
            #pragma unroll
            for (int mt = 0; mt < 2; mt++) {
                uint32_t ao = stb + swz(rowA0 + mt * 16, u0a + 2 * ks);
                ldsm4(ah[mt], ao);
                ldsm4(al[mt], ao + 8192);
            }
            #pragma unroll
            for (int ntp = 0; ntp < 2; ntp++) {
                uint32_t b1h[4], b1l[4], b3h[4], b3l[4];
                uint32_t bo = stb + 16384 + swz(rowB0 + ntp * 16, u0b + 2 * ks);
                ldsm4(b1h, bo);
                ldsm4(b1l, bo + 4096);
                ldsm4(b3h, bo + 8192);
                ldsm4(b3l, bo + 12288);
                #pragma unroll
                for (int half = 0; half < 2; half++) {
                    int nt = ntp * 2 + half;
                    #pragma unroll
                    for (int mt = 0; mt < 2; mt++) {
                        mma_bf16(acc1[mt][nt], ah[mt], b1h[half * 2], b1h[half * 2 + 1]);
                        mma_bf16(acc1[mt][nt], ah[mt], b1l[half * 2], b1l[half * 2 + 1]);
                        mma_bf16(acc1[mt][nt], al[mt], b1h[half * 2], b1h[half * 2 + 1]);
                        mma_bf16(acc3[mt][nt], ah[mt], b3h[half * 2], b3h[half * 2 + 1]);
                        mma_bf16(acc3[mt][nt], ah[mt], b3l[half * 2], b3l[half * 2 + 1]);
                        mma_bf16(acc3[mt][nt], al[mt], b3h[half * 2], b3h[half * 2 + 1]);
                    }
                }
            }
        }
    }

    // epilogue: silu(acc1) * acc3 -> split -> g_Hh / g_Hl
    #pragma unroll
    for (int mt = 0; mt < 2; mt++) {
        int rl = warp_m * 32 + mt * 16 + g;
        int pid0 = rows[rl], pid1 = rows[rl + 8];
        #pragma unroll
        for (int nt = 0; nt < 4; nt++) {
            int col = n0 + warp_n * 32 + nt * 8 + 2 * t4;
            if (pid0 >= 0) {
                float z0 = acc1[mt][nt][0], z1 = acc1[mt][nt][1];
                float o0 = z0 / (1.f + __expf(-z0)) * acc3[mt][nt][0];
                float o1 = z1 / (1.f + __expf(-z1)) * acc3[mt][nt][1];
                uint32_t h, l;
                split2(o0, o1, h, l);
                *(uint32_t*)(g_Hh + (size_t)pid0 * DFF + col) = h;
                *(uint32_t*)(g_Hl + (size_t)pid0 * DFF + col) = l;
            }
            if (pid1 >= 0) {
                float z2 = acc1[mt][nt][2], z3 = acc1[mt][nt][3];
                float o2 = z2 / (1.f + __expf(-z2)) * acc3[mt][nt][2];
                float o3 = z3 / (1.f + __expf(-z3)) * acc3[mt][nt][3];
                uint32_t h, l;
                split2(o2, o3, h, l);
                *(uint32_t*)(g_Hh + (size_t)pid1 * DFF + col) = h;
                *(uint32_t*)(g_Hl + (size_t)pid1 * DFF + col) = l;
            }
        }
    }
}

// =====================  GEMM2: Y = Hg W2^T  ====================================
__global__ void __launch_bounds__(256, 2) gemm2_tc() {
    int e = blockIdx.z;
    int c = g_cnt[e];
    int mt0 = blockIdx.x;
    if (mt0 * 128 >= c) return;
    int n0 = blockIdx.y * 64;

    extern __shared__ __align__(128) char smem[];
    __shared__ int rows[128];

    int tid = threadIdx.x;
    if (tid < 128) {
        int pos = mt0 * 128 + tid;
        rows[tid] = (pos < c) ? g_list[e * TMAX + pos] : -1;
    }
    __syncthreads();

    int lane = tid & 31, warp = tid >> 5;
    int warp_m = warp & 3, warp_n = warp >> 2;
    int g = lane >> 2, t4 = lane & 3;

    uint32_t sb = smem_u32(smem);
    int rowA0 = warp_m * 32 + (lane & 15);
    int u0a = lane >> 4;
    int rowB0 = warp_n * 32 + (lane & 7) + ((lane & 16) ? 8 : 0);
    int u0b = (lane >> 3) & 1;

    float acc[2][4][4];
    #pragma unroll
    for (int i = 0; i < 2; i++)
        #pragma unroll
        for (int j = 0; j < 4; j++)
            #pragma unroll
            for (int k = 0; k < 4; k++) acc[i][j][k] = 0.f;

    const size_t wbase = ((size_t)e * DMODEL + n0) * DFF;

    auto ISSUE = [&](int s) {
        uint32_t stb = sb + (uint32_t)(s % 3) * G2_STG;
        #pragma unroll
        for (int i = 0; i < 4; i++) {
            int idx = tid + 256 * i;
            int r = idx >> 3, sub = idx & 7, grp = sub & 3, hf = sub >> 2;
            int pid = rows[r];
            const __nv_bfloat16* base = hf ? g_Hl : g_Hh;
            const void* sp = (pid >= 0)
                ? (const void*)(base + (size_t)pid * DFF + s * BK + grp * 8)
                : (const void*)base;
            cpa16(stb + hf * 8192 + swz(r, grp), sp, pid >= 0);
        }
        #pragma unroll
        for (int i = 0; i < 2; i++) {
            int idx = tid + 256 * i;
            int hf = idx >> 8, rem = idx & 255, r = rem >> 2, grp = rem & 3;
            const __nv_bfloat16* base = hf ? g_w2l : g_w2h;
            const void* sp = base + wbase + (size_t)r * DFF + s * BK + grp * 8;
            cpa16(stb + 16384 + hf * 4096 + swz(r, grp), sp, true);
        }
    };

    const int NS = DFF / BK;   // 64
    ISSUE(0); CP_COMMIT();
    ISSUE(1); CP_COMMIT();
    for (int s = 0; s < NS; s++) {
        CP_WAIT(1);
        __syncthreads();
        if (s + 2 < NS) ISSUE(s + 2);
        CP_COMMIT();

        uint32_t stb = sb + (uint32_t)(s % 3) * G2_STG;
        #pragma unroll
        for (int ks = 0; ks < 2; ks++) {
            uint32_t ah[2][4], al[2][4];
            #pragma unroll
            for (int mt = 0; mt < 2; mt++) {
                uint32_t ao = stb + swz(rowA0 + mt * 16, u0a + 2 * ks);
                ldsm4(ah[mt], ao);
                ldsm4(al[mt], ao + 8192);
            }
            #pragma unroll
            for (int ntp = 0; ntp < 2; ntp++) {
                uint32_t bh[4], bl[4];
                uint32_t bo = stb + 16384 + swz(rowB0 + ntp * 16, u0b + 2 * ks);
                ldsm4(bh, bo);
                ldsm4(bl, bo + 4096);
                #pragma unroll
                for (int half = 0; half < 2; half++) {
                    int nt = ntp * 2 + half;
                    #pragma unroll
                    for (int mt = 0; mt < 2; mt++) {
                        mma_bf16(acc[mt][nt], ah[mt], bh[half * 2], bh[half * 2 + 1]);
                        mma_bf16(acc[mt][nt], ah[mt], bl[half * 2], bl[half * 2 + 1]);
                        mma_bf16(acc[mt][nt], al[mt], bh[half * 2], bh[half * 2 + 1]);
                    }
                }
            }
        }
    }

    #pragma unroll
    for (int mt = 0; mt < 2; mt++) {
        int rl = warp_m * 32 + mt * 16 + g;
        int pid0 = rows[rl], pid1 = rows[rl + 8];
        #pragma unroll
        for (int nt = 0; nt < 4; nt++) {
            int col = n0 + warp_n * 32 + nt * 8 + 2 * t4;
            if (pid0 >= 0)
                *(float2*)(g_Y + (size_t)pid0 * DMODEL + col) =
                    make_float2(acc[mt][nt][0], acc[mt][nt][1]);
            if (pid1 >= 0)
                *(float2*)(g_Y + (size_t)pid1 * DMODEL + col) =
                    make_float2(acc[mt][nt][2], acc[mt][nt][3]);
        }
    }
}

// ---------------- per-token dual LayerNorm + combine ---------------------------
__global__ void __launch_bounds__(256) ln2_kernel(
    const float* __restrict__ ln_g, const float* __restrict__ ln_b,
    float* __restrict__ out) {
    int t = blockIdx.x;
    int e0 = g_tok_e[2 * t], e1 = g_tok_e[2 * t + 1];
    float c0 = g_tok_c[2 * t], c1 = g_tok_c[2 * t + 1];
    const float* y0 = g_Y + (size_t)(2 * t) * DMODEL;
    const float* y1 = g_Y + (size_t)(2 * t + 1) * DMODEL;

    __shared__ float red[16];
    int lane = threadIdx.x & 31, warp = threadIdx.x >> 5;

    float v0[4], v1[4];
    float s0 = 0.f, s1 = 0.f;
    #pragma unroll
    for (int i = 0; i < 4; i++) {
        int col = threadIdx.x + i * 256;
        v0[i] = y0[col]; s0 += v0[i];
        v1[i] = y1[col]; s1 += v1[i];
    }
    #pragma unroll
    for (int o = 16; o; o >>= 1) {
        s0 += __shfl_xor_sync(0xffffffffu, s0, o);
        s1 += __shfl_xor_sync(0xffffffffu, s1, o);
    }
    if (lane == 0) { red[warp] = s0; red[8 + warp] = s1; }
    __syncthreads();
    float m0 = 0.f, m1 = 0.f;
    #pragma unroll
    for (int i = 0; i < 8; i++) { m0 += red[i]; m1 += red[8 + i]; }
    float mu0 = m0 * (1.f / DMODEL), mu1 = m1 * (1.f / DMODEL);
    __syncthreads();

    float q0 = 0.f, q1 = 0.f;
    #pragma unroll
    for (int i = 0; i < 4; i++) {
        float d0 = v0[i] - mu0; q0 += d0 * d0;
        float d1 = v1[i] - mu1; q1 += d1 * d1;
    }
    #pragma unroll
    for (int o = 16; o; o >>= 1) {
        q0 += __shfl_xor_sync(0xffffffffu, q0, o);
        q1 += __shfl_xor_sync(0xffffffffu, q1, o);
    }
    if (lane == 0) { red[warp] = q0; red[8 + warp] = q1; }
    __syncthreads();
    float t0 = 0.f, t1 = 0.f;
    #pragma unroll
    for (int i = 0; i < 8; i++) { t0 += red[i]; t1 += red[8 + i]; }
    float rstd0 = rsqrtf(t0 * (1.f / DMODEL) + LN_EPS);
    float rstd1 = rsqrtf(t1 * (1.f / DMODEL) + LN_EPS);

    const float* ga = ln_g + (size_t)e0 * DMODEL;
    const float* ba = ln_b + (size_t)e0 * DMODEL;
    const float* gb = ln_g + (size_t)e1 * DMODEL;
    const float* bb = ln_b + (size_t)e1 * DMODEL;
    #pragma unroll
    for (int i = 0; i < 4; i++) {
        int col = threadIdx.x + i * 256;
        float yn0 = (v0[i] - mu0) * rstd0 * ga[col] + ba[col];
        float yn1 = (v1[i] - mu1) * rstd1 * gb[col] + bb[col];
        out[(size_t)t * DMODEL + col] = c0 * yn0 + c1 * yn1;
    }
}

// ---------------- launch --------------------------------------------------------
extern "C" void kernel_launch(void* const* d_in, const int* in_sizes, int n_in,
                              void* d_out, int out_size) {
    const float* x  = (const float*)d_in[0];
    const float* rw = (const float*)d_in[1];
    const float* rb = (const float*)d_in[2];
    const float* w1 = (const float*)d_in[3];
    const float* w2 = (const float*)d_in[4];
    const float* w3 = (const float*)d_in[5];
    const float* lg = (const float*)d_in[6];
    const float* lb = (const float*)d_in[7];
    float* out = (float*)d_out;

    int T = in_sizes[0] / DMODEL;   // 4096

    cudaFuncSetAttribute(gemm1_tc, cudaFuncAttributeMaxDynamicSharedMemorySize, G1_SMEM);
    cudaFuncSetAttribute(gemm2_tc, cudaFuncAttributeMaxDynamicSharedMemorySize, G2_SMEM);
    cudaFuncSetAttribute(gemm1_tc, cudaFuncAttributePreferredSharedMemoryCarveout,
                         cudaSharedmemCarveoutMaxShared);
    cudaFuncSetAttribute(gemm2_tc, cudaFuncAttributePreferredSharedMemoryCarveout,
                         cudaSharedmemCarveoutMaxShared);

    init_kernel<<<1, 32>>>();

    // pre-split weights + x to bf16 hi/lo
    {
        __nv_bfloat16 *w1h, *w1l, *w3h, *w3l, *w2h, *w2l, *xh, *xl;
        cudaGetSymbolAddress((void**)&w1h, g_w1h);
        cudaGetSymbolAddress((void**)&w1l, g_w1l);
        cudaGetSymbolAddress((void**)&w3h, g_w3h);
        cudaGetSymbolAddress((void**)&w3l, g_w3l);
        cudaGetSymbolAddress((void**)&w2h, g_w2h);
        cudaGetSymbolAddress((void**)&w2l, g_w2l);
        cudaGetSymbolAddress((void**)&xh,  g_xh);
        cudaGetSymbolAddress((void**)&xl,  g_xl);

        int nw4 = (int)((size_t)E_EXP * DFF * DMODEL / 4);   // 8388608
        int nx4 = (int)((size_t)T * DMODEL / 4);             // 1048576
        split_kernel<<<nw4 / 256, 256>>>((const float4*)w1, (uint2*)w1h, (uint2*)w1l, nw4);
        split_kernel<<<nw4 / 256, 256>>>((const float4*)w3, (uint2*)w3h, (uint2*)w3l, nw4);
        split_kernel<<<nw4 / 256, 256>>>((const float4*)w2, (uint2*)w2h, (uint2*)w2l, nw4);
        split_kernel<<<(nx4 + 255) / 256, 256>>>((const float4*)x, (uint2*)xh, (uint2*)xl, nx4);
    }

    router_kernel<<<T, 128>>>(x, rw, rb);

    dim3 g1((T + 127) / 128, DFF / 64, E_EXP);
    gemm1_tc<<<g1, 256, G1_SMEM>>>();

    dim3 g2((T + 127) / 128, DMODEL / 64, E_EXP);
    gemm2_tc<<<g2, 256, G2_SMEM>>>();

    ln2_kernel<<<T, 256>>>(lg, lb, out);
}

// round 8
// speedup vs baseline: 5.2443x; 1.3355x over previous
#include <cuda_runtime.h>
#include <cuda_fp16.h>
#include <cstdint>

// Problem constants
#define E_EXP 16
#define DMODEL 1024
#define DFF 2048
#define TMAX 4096
#define LN_EPS 1e-5f

#define BK 32          // fp32 elements per K-chunk

// ---------------- scratch (device globals) ------------------------------------
__device__ int   g_cnt[E_EXP];
__device__ int   g_list[E_EXP * TMAX];             // pid = token*2 + slot
__device__ int   g_tok_e[2 * TMAX];
__device__ float g_tok_c[2 * TMAX];
__device__ float g_Y[(size_t)2 * TMAX * DMODEL];   // [pid][D]

// fp16 tensors: activations split hi/lo, weights hi only
__device__ __align__(16) __half g_xh[(size_t)TMAX * DMODEL];
__device__ __align__(16) __half g_xl[(size_t)TMAX * DMODEL];
__device__ __align__(16) __half g_w1h[(size_t)E_EXP * DFF * DMODEL];
__device__ __align__(16) __half g_w3h[(size_t)E_EXP * DFF * DMODEL];
__device__ __align__(16) __half g_w2h[(size_t)E_EXP * DMODEL * DFF];
__device__ __align__(16) __half g_Hh[(size_t)2 * TMAX * DFF];
__device__ __align__(16) __half g_Hl[(size_t)2 * TMAX * DFF];

// ---------------- helpers -------------------------------------------------------
__device__ __forceinline__ uint32_t smem_u32(const void* p) {
    uint32_t a;
    asm("{ .reg .u64 t; cvta.to.shared.u64 t, %1; cvt.u32.u64 %0, t; }" : "=r"(a) : "l"(p));
    return a;
}

__device__ __forceinline__ void mma_f16(float* c, const uint32_t* a,
                                        uint32_t b0, uint32_t b1) {
    asm volatile(
        "mma.sync.aligned.m16n8k16.row.col.f32.f16.f16.f32 "
        "{%0,%1,%2,%3}, {%4,%5,%6,%7}, {%8,%9}, {%0,%1,%2,%3};\n"
        : "+f"(c[0]), "+f"(c[1]), "+f"(c[2]), "+f"(c[3])
        : "r"(a[0]), "r"(a[1]), "r"(a[2]), "r"(a[3]), "r"(b0), "r"(b1));
}

__device__ __forceinline__ void ldsm4(uint32_t* r, uint32_t a) {
    asm volatile("ldmatrix.sync.aligned.m8n8.x4.shared.b16 {%0,%1,%2,%3}, [%4];"
        : "=r"(r[0]), "=r"(r[1]), "=r"(r[2]), "=r"(r[3]) : "r"(a));
}

__device__ __forceinline__ uint32_t pack2h(float x, float y) {
    __half hx = __float2half_rn(x), hy = __float2half_rn(y);
    return (uint32_t)__half_as_ushort(hx) | ((uint32_t)__half_as_ushort(hy) << 16);
}

__device__ __forceinline__ void split2f(float x, float y, uint32_t& h, uint32_t& l) {
    __half hx = __float2half_rn(x);
    __half hy = __float2half_rn(y);
    __half lx = __float2half_rn(x - __half2float(hx));
    __half ly = __float2half_rn(y - __half2float(hy));
    h = (uint32_t)__half_as_ushort(hx) | ((uint32_t)__half_as_ushort(hy) << 16);
    l = (uint32_t)__half_as_ushort(lx) | ((uint32_t)__half_as_ushort(ly) << 16);
}

__device__ __forceinline__ void cpa16(uint32_t dst, const void* src, bool v) {
    int sz = v ? 16 : 0;
    asm volatile("cp.async.cg.shared.global [%0], [%1], 16, %2;\n"
                 :: "r"(dst), "l"(src), "r"(sz));
}
#define CP_COMMIT() asm volatile("cp.async.commit_group;\n" ::: "memory")
#define CP_WAIT(n)  asm volatile("cp.async.wait_group %0;\n" :: "n"(n) : "memory")

// physical smem offset of logical (row, 16B-unit) under XOR swizzle, 64B rows
__device__ __forceinline__ uint32_t swz(int row, int unit) {
    return (uint32_t)(row * 64 + ((unit ^ ((row & 7) >> 1)) << 4));
}

// ---------------- init + splits --------------------------------------------------
__global__ void init_kernel() {
    if (threadIdx.x < E_EXP) g_cnt[threadIdx.x] = 0;
}

// weights: fp16 hi only
__global__ void splith_kernel(const float4* __restrict__ src,
                              uint2* __restrict__ dh, int n4) {
    int i = blockIdx.x * blockDim.x + threadIdx.x;
    if (i >= n4) return;
    float4 v = src[i];
    dh[i] = make_uint2(pack2h(v.x, v.y), pack2h(v.z, v.w));
}

// activations: fp16 hi + lo
__global__ void splitx_kernel(const float4* __restrict__ src,
                              uint2* __restrict__ dh, uint2* __restrict__ dl,
                              int n4) {
    int i = blockIdx.x * blockDim.x + threadIdx.x;
    if (i >= n4) return;
    float4 v = src[i];
    uint32_t h0, l0, h1, l1;
    split2f(v.x, v.y, h0, l0);
    split2f(v.z, v.w, h1, l1);
    dh[i] = make_uint2(h0, h1);
    dl[i] = make_uint2(l0, l1);
}

// ---------------- router --------------------------------------------------------
__global__ void __launch_bounds__(128) router_kernel(
    const float* __restrict__ x, const float* __restrict__ rw,
    const float* __restrict__ rb) {
    int t = blockIdx.x;
    __shared__ float xs[DMODEL];
    __shared__ float logits[E_EXP];
    const float* xr = x + (size_t)t * DMODEL;
    for (int i = threadIdx.x; i < DMODEL; i += blockDim.x) xs[i] = xr[i];
    __syncthreads();

    int warp = threadIdx.x >> 5, lane = threadIdx.x & 31;
    for (int e = warp; e < E_EXP; e += 4) {
        const float* w = rw + (size_t)e * DMODEL;
        float s = 0.f;
        for (int k = lane; k < DMODEL; k += 32) s += xs[k] * w[k];
        #pragma unroll
        for (int o = 16; o; o >>= 1) s += __shfl_xor_sync(0xffffffffu, s, o);
        if (lane == 0) logits[e] = s + rb[e];
    }
    __syncthreads();

    if (threadIdx.x == 0) {
        float m = -1e30f;
        #pragma unroll
        for (int e = 0; e < E_EXP; e++) m = fmaxf(m, logits[e]);
        float p[E_EXP];
        #pragma unroll
        for (int e = 0; e < E_EXP; e++) p[e] = __expf(logits[e] - m);
        int e0 = 0;
        #pragma unroll
        for (int e = 1; e < E_EXP; e++) if (p[e] > p[e0]) e0 = e;
        int e1 = (e0 == 0) ? 1 : 0;
        #pragma unroll
        for (int e = 0; e < E_EXP; e++) {
            if (e == e0 || e == e1) continue;
            if (p[e] > p[e1]) e1 = e;
        }
        float s01 = p[e0] + p[e1];
        float c0 = p[e0] / s01, c1 = p[e1] / s01;
        int pos0 = atomicAdd(&g_cnt[e0], 1);
        g_list[e0 * TMAX + pos0] = t * 2 + 0;
        int pos1 = atomicAdd(&g_cnt[e1], 1);
        g_list[e1 * TMAX + pos1] = t * 2 + 1;
        g_tok_e[2 * t + 0] = e0; g_tok_c[2 * t + 0] = c0;
        g_tok_e[2 * t + 1] = e1; g_tok_c[2 * t + 1] = c1;
    }
}

// stage byte layout (64B rows, swizzled):
//   gemm1: Ah 0 (128 rows, 8KB) | Al 8192 | W1h 16384 (64 rows, 4KB) | W3h 20480
//   gemm2: Ah 0 | Al 8192 | Wh 16384
#define G1_STG 24576
#define G1_SMEM (3 * G1_STG)
#define G2_STG 20480
#define G2_SMEM (3 * G2_STG)

// =====================  GEMM1: H = silu(Xg W1^T) * (Xg W3^T)  ==================
__global__ void __launch_bounds__(256, 2) gemm1_tc() {
    int e = blockIdx.z;
    int c = g_cnt[e];
    int mt0 = blockIdx.x;
    if (mt0 * 128 >= c) return;
    int n0 = blockIdx.y * 64;

    extern __shared__ __align__(128) char smem[];
    __shared__ int rows[128];

    int tid = threadIdx.x;
    if (tid < 128) {
        int pos = mt0 * 128 + tid;
        rows[tid] = (pos < c) ? g_list[e * TMAX + pos] : -1;
    }
    __syncthreads();

    int lane = tid & 31, warp = tid >> 5;
    int warp_m = warp & 3, warp_n = warp >> 2;     // 4x2 warp grid
    int g = lane >> 2, t4 = lane & 3;

    uint32_t sb = smem_u32(smem);
    int rowA0 = warp_m * 32 + (lane & 15);         // + mt*16
    int u0a = lane >> 4;                            // 0/1
    int rowB0 = warp_n * 32 + (lane & 7) + ((lane & 16) ? 8 : 0);  // + ntp*16
    int u0b = (lane >> 3) & 1;

    float acc1[2][4][4], acc3[2][4][4];
    #pragma unroll
    for (int i = 0; i < 2; i++)
        #pragma unroll
        for (int j = 0; j < 4; j++)
            #pragma unroll
            for (int k = 0; k < 4; k++) { acc1[i][j][k] = 0.f; acc3[i][j][k] = 0.f; }

    const size_t wbase = ((size_t)e * DFF + n0) * DMODEL;

    auto ISSUE = [&](int s) {
        uint32_t stb = sb + (uint32_t)(s % 3) * G1_STG;
        // A hi/lo: 128 rows x 4 units x 2 halves = 1024 copies
        #pragma unroll
        for (int i = 0; i < 4; i++) {
            int idx = tid + 256 * i;
            int r = idx >> 3, sub = idx & 7, grp = sub & 3, hf = sub >> 2;
            int pid = rows[r];
            const __half* base = hf ? g_xl : g_xh;
            const void* sp = (pid >= 0)
                ? (const void*)(base + (size_t)(pid >> 1) * DMODEL + s * BK + grp * 8)
                : (const void*)base;
            cpa16(stb + hf * 8192 + swz(r, grp), sp, pid >= 0);
        }
        // W1 hi: 64 rows x 4 units = 256 copies
        {
            int r = tid >> 2, grp = tid & 3;
            const void* sp = g_w1h + wbase + (size_t)r * DMODEL + s * BK + grp * 8;
            cpa16(stb + 16384 + swz(r, grp), sp, true);
        }
        // W3 hi: 256 copies
        {
            int r = tid >> 2, grp = tid & 3;
            const void* sp = g_w3h + wbase + (size_t)r * DMODEL + s * BK + grp * 8;
            cpa16(stb + 20480 + swz(r, grp), sp, true);
        }
    };

    const int NS = DMODEL / BK;   // 32
    ISSUE(0); CP_COMMIT();
    ISSUE(1); CP_COMMIT();
    for (int s = 0; s < NS; s++) {
        CP_WAIT(1);
        __syncthreads();
        if (s + 2 < NS) ISSUE(s + 2);
        CP_COMMIT();

        uint32_t stb = sb + (uint32_t)(s % 3) * G1_STG;
        #pragma unroll
        for (int ks = 0; ks < 2; ks++) {
            uint32_t ah[2][4], al[2][4];
            #pragma unroll
            for (int mt = 0; mt < 2; mt++) {
                uint32_t ao = stb + swz(rowA0 + mt * 16, u0a + 2 * ks);
                ldsm4(ah[mt], ao);
                ldsm4(al[mt], ao + 8192);
            }
            #pragma unroll
            for (int ntp = 0; ntp < 2; ntp++) {
                uint32_t b1[4], b3[4];
                uint32_t bo = stb + 16384 + swz(rowB0 + ntp * 16, u0b + 2 * ks);
                ldsm4(b1, bo);
                ldsm4(b3, bo + 4096);
                #pragma unroll
                for (int half = 0; half < 2; half++) {
                    int nt = ntp * 2 + half;
                    #pragma unroll
                    for (int mt = 0; mt < 2; mt++) {
                        mma_f16(acc1[mt][nt], ah[mt], b1[half * 2], b1[half * 2 + 1]);
                        mma_f16(acc1[mt][nt], al[mt], b1[half * 2], b1[half * 2 + 1]);
                        mma_f16(acc3[mt][nt], ah[mt], b3[half * 2], b3[half * 2 + 1]);
                        mma_f16(acc3[mt][nt], al[mt], b3[half * 2], b3[half * 2 + 1]);
                    }
                }
            }
        }
    }

    // epilogue: silu(acc1) * acc3 -> fp16 split -> g_Hh / g_Hl
    #pragma unroll
    for (int mt = 0; mt < 2; mt++) {
        int rl = warp_m * 32 + mt * 16 + g;
        int pid0 = rows[rl], pid1 = rows[rl + 8];
        #pragma unroll
        for (int nt = 0; nt < 4; nt++) {
            int col = n0 + warp_n * 32 + nt * 8 + 2 * t4;
            if (pid0 >= 0) {
                float z0 = acc1[mt][nt][0], z1 = acc1[mt][nt][1];
                float o0 = z0 / (1.f + __expf(-z0)) * acc3[mt][nt][0];
                float o1 = z1 / (1.f + __expf(-z1)) * acc3[mt][nt][1];
                uint32_t h, l;
                split2f(o0, o1, h, l);
                *(uint32_t*)(g_Hh + (size_t)pid0 * DFF + col) = h;
                *(uint32_t*)(g_Hl + (size_t)pid0 * DFF + col) = l;
            }
            if (pid1 >= 0) {
                float z2 = acc1[mt][nt][2], z3 = acc1[mt][nt][3];
                float o2 = z2 / (1.f + __expf(-z2)) * acc3[mt][nt][2];
                float o3 = z3 / (1.f + __expf(-z3)) * acc3[mt][nt][3];
                uint32_t h, l;
                split2f(o2, o3, h, l);
                *(uint32_t*)(g_Hh + (size_t)pid1 * DFF + col) = h;
                *(uint32_t*)(g_Hl + (size_t)pid1 * DFF + col) = l;
            }
        }
    }
}

// =====================  GEMM2: Y = Hg W2^T  ====================================
__global__ void __launch_bounds__(256, 2) gemm2_tc() {
    int e = blockIdx.z;
    int c = g_cnt[e];
    int mt0 = blockIdx.x;
    if (mt0 * 128 >= c) return;
    int n0 = blockIdx.y * 64;

    extern __shared__ __align__(128) char smem[];
    __shared__ int rows[128];

    int tid = threadIdx.x;
    if (tid < 128) {
        int pos = mt0 * 128 + tid;
        rows[tid] = (pos < c) ? g_list[e * TMAX + pos] : -1;
    }
    __syncthreads();

    int lane = tid & 31, warp = tid >> 5;
    int warp_m = warp & 3, warp_n = warp >> 2;
    int g = lane >> 2, t4 = lane & 3;

    uint32_t sb = smem_u32(smem);
    int rowA0 = warp_m * 32 + (lane & 15);
    int u0a = lane >> 4;
    int rowB0 = warp_n * 32 + (lane & 7) + ((lane & 16) ? 8 : 0);
    int u0b = (lane >> 3) & 1;

    float acc[2][4][4];
    #pragma unroll
    for (int i = 0; i < 2; i++)
        #pragma unroll
        for (int j = 0; j < 4; j++)
            #pragma unroll
            for (int k = 0; k < 4; k++) acc[i][j][k] = 0.f;

    const size_t wbase = ((size_t)e * DMODEL + n0) * DFF;

    auto ISSUE = [&](int s) {
        uint32_t stb = sb + (uint32_t)(s % 3) * G2_STG;
        #pragma unroll
        for (int i = 0; i < 4; i++) {
            int idx = tid + 256 * i;
            int r = idx >> 3, sub = idx & 7, grp = sub & 3, hf = sub >> 2;
            int pid = rows[r];
            const __half* base = hf ? g_Hl : g_Hh;
            const void* sp = (pid >= 0)
                ? (const void*)(base + (size_t)pid * DFF + s * BK + grp * 8)
                : (const void*)base;
            cpa16(stb + hf * 8192 + swz(r, grp), sp, pid >= 0);
        }
        {
            int r = tid >> 2, grp = tid & 3;
            const void* sp = g_w2h + wbase + (size_t)r * DFF + s * BK + grp * 8;
            cpa16(stb + 16384 + swz(r, grp), sp, true);
        }
    };

    const int NS = DFF / BK;   // 64
    ISSUE(0); CP_COMMIT();
    ISSUE(1); CP_COMMIT();
    for (int s = 0; s < NS; s++) {
        CP_WAIT(1);
        __syncthreads();
        if (s + 2 < NS) ISSUE(s + 2);
        CP_COMMIT();

        uint32_t stb = sb + (uint32_t)(s % 3) * G2_STG;
        #pragma unroll
        for (int ks = 0; ks < 2; ks++) {
            uint32_t ah[2][4], al[2][4];
            #pragma unroll
            for (int mt = 0; mt < 2; mt++) {
                uint32_t ao = stb + swz(rowA0 + mt * 16, u0a + 2 * ks);
                ldsm4(ah[mt], ao);
                ldsm4(al[mt], ao + 8192);
            }
            #pragma unroll
            for (int ntp = 0; ntp < 2; ntp++) {
                uint32_t bh[4];
                uint32_t bo = stb + 16384 + swz(rowB0 + ntp * 16, u0b + 2 * ks);
                ldsm4(bh, bo);
                #pragma unroll
                for (int half = 0; half < 2; half++) {
                    int nt = ntp * 2 + half;
                    #pragma unroll
                    for (int mt = 0; mt < 2; mt++) {
                        mma_f16(acc[mt][nt], ah[mt], bh[half * 2], bh[half * 2 + 1]);
                        mma_f16(acc[mt][nt], al[mt], bh[half * 2], bh[half * 2 + 1]);
                    }
                }
            }
        }
    }

    #pragma unroll
    for (int mt = 0; mt < 2; mt++) {
        int rl = warp_m * 32 + mt * 16 + g;
        int pid0 = rows[rl], pid1 = rows[rl + 8];
        #pragma unroll
        for (int nt = 0; nt < 4; nt++) {
            int col = n0 + warp_n * 32 + nt * 8 + 2 * t4;
            if (pid0 >= 0)
                *(float2*)(g_Y + (size_t)pid0 * DMODEL + col) =
                    make_float2(acc[mt][nt][0], acc[mt][nt][1]);
            if (pid1 >= 0)
                *(float2*)(g_Y + (size_t)pid1 * DMODEL + col) =
                    make_float2(acc[mt][nt][2], acc[mt][nt][3]);
        }
    }
}

// ---------------- per-token dual LayerNorm + combine ---------------------------
__global__ void __launch_bounds__(256) ln2_kernel(
    const float* __restrict__ ln_g, const float* __restrict__ ln_b,
    float* __restrict__ out) {
    int t = blockIdx.x;
    int e0 = g_tok_e[2 * t], e1 = g_tok_e[2 * t + 1];
    float c0 = g_tok_c[2 * t], c1 = g_tok_c[2 * t + 1];
    const float* y0 = g_Y + (size_t)(2 * t) * DMODEL;
    const float* y1 = g_Y + (size_t)(2 * t + 1) * DMODEL;

    __shared__ float red[16];
    int lane = threadIdx.x & 31, warp = threadIdx.x >> 5;

    float v0[4], v1[4];
    float s0 = 0.f, s1 = 0.f;
    #pragma unroll
    for (int i = 0; i < 4; i++) {
        int col = threadIdx.x + i * 256;
        v0[i] = y0[col]; s0 += v0[i];
        v1[i] = y1[col]; s1 += v1[i];
    }
    #pragma unroll
    for (int o = 16; o; o >>= 1) {
        s0 += __shfl_xor_sync(0xffffffffu, s0, o);
        s1 += __shfl_xor_sync(0xffffffffu, s1, o);
    }
    if (lane == 0) { red[warp] = s0; red[8 + warp] = s1; }
    __syncthreads();
    float m0 = 0.f, m1 = 0.f;
    #pragma unroll
    for (int i = 0; i < 8; i++) { m0 += red[i]; m1 += red[8 + i]; }
    float mu0 = m0 * (1.f / DMODEL), mu1 = m1 * (1.f / DMODEL);
    __syncthreads();

    float q0 = 0.f, q1 = 0.f;
    #pragma unroll
    for (int i = 0; i < 4; i++) {
        float d0 = v0[i] - mu0; q0 += d0 * d0;
        float d1 = v1[i] - mu1; q1 += d1 * d1;
    }
    #pragma unroll
    for (int o = 16; o; o >>= 1) {
        q0 += __shfl_xor_sync(0xffffffffu, q0, o);
        q1 += __shfl_xor_sync(0xffffffffu, q1, o);
    }
    if (lane == 0) { red[warp] = q0; red[8 + warp] = q1; }
    __syncthreads();
    float t0 = 0.f, t1 = 0.f;
    #pragma unroll
    for (int i = 0; i < 8; i++) { t0 += red[i]; t1 += red[8 + i]; }
    float rstd0 = rsqrtf(t0 * (1.f / DMODEL) + LN_EPS);
    float rstd1 = rsqrtf(t1 * (1.f / DMODEL) + LN_EPS);

    const float* ga = ln_g + (size_t)e0 * DMODEL;
    const float* ba = ln_b + (size_t)e0 * DMODEL;
    const float* gb = ln_g + (size_t)e1 * DMODEL;
    const float* bb = ln_b + (size_t)e1 * DMODEL;
    #pragma unroll
    for (int i = 0; i < 4; i++) {
        int col = threadIdx.x + i * 256;
        float yn0 = (v0[i] - mu0) * rstd0 * ga[col] + ba[col];
        float yn1 = (v1[i] - mu1) * rstd1 * gb[col] + bb[col];
        out[(size_t)t * DMODEL + col] = c0 * yn0 + c1 * yn1;
    }
}

// ---------------- launch --------------------------------------------------------
extern "C" void kernel_launch(void* const* d_in, const int* in_sizes, int n_in,
                              void* d_out, int out_size) {
    const float* x  = (const float*)d_in[0];
    const float* rw = (const float*)d_in[1];
    const float* rb = (const float*)d_in[2];
    const float* w1 = (const float*)d_in[3];
    const float* w2 = (const float*)d_in[4];
    const float* w3 = (const float*)d_in[5];
    const float* lg = (const float*)d_in[6];
    const float* lb = (const float*)d_in[7];
    float* out = (float*)d_out;

    int T = in_sizes[0] / DMODEL;   // 4096

    cudaFuncSetAttribute(gemm1_tc, cudaFuncAttributeMaxDynamicSharedMemorySize, G1_SMEM);
    cudaFuncSetAttribute(gemm2_tc, cudaFuncAttributeMaxDynamicSharedMemorySize, G2_SMEM);
    cudaFuncSetAttribute(gemm1_tc, cudaFuncAttributePreferredSharedMemoryCarveout,
                         cudaSharedmemCarveoutMaxShared);
    cudaFuncSetAttribute(gemm2_tc, cudaFuncAttributePreferredSharedMemoryCarveout,
                         cudaSharedmemCarveoutMaxShared);

    init_kernel<<<1, 32>>>();

    // convert weights (hi only) + split x (hi/lo) to fp16
    {
        __half *w1h, *w3h, *w2h, *xh, *xl;
        cudaGetSymbolAddress((void**)&w1h, g_w1h);
        cudaGetSymbolAddress((void**)&w3h, g_w3h);
        cudaGetSymbolAddress((void**)&w2h, g_w2h);
        cudaGetSymbolAddress((void**)&xh,  g_xh);
        cudaGetSymbolAddress((void**)&xl,  g_xl);

        int nw4 = (int)((size_t)E_EXP * DFF * DMODEL / 4);   // 8388608
        int nx4 = (int)((size_t)T * DMODEL / 4);             // 1048576
        splith_kernel<<<nw4 / 256, 256>>>((const float4*)w1, (uint2*)w1h, nw4);
        splith_kernel<<<nw4 / 256, 256>>>((const float4*)w3, (uint2*)w3h, nw4);
        splith_kernel<<<nw4 / 256, 256>>>((const float4*)w2, (uint2*)w2h, nw4);
        splitx_kernel<<<(nx4 + 255) / 256, 256>>>((const float4*)x, (uint2*)xh, (uint2*)xl, nx4);
    }

    router_kernel<<<T, 128>>>(x, rw, rb);

    dim3 g1((T + 127) / 128, DFF / 64, E_EXP);
    gemm1_tc<<<g1, 256, G1_SMEM>>>();

    dim3 g2((T + 127) / 128, DMODEL / 64, E_EXP);
    gemm2_tc<<<g2, 256, G2_SMEM>>>();

    ln2_kernel<<<T, 256>>>(lg, lb, out);
}